// round 1
// baseline (speedup 1.0000x reference)
#include <cuda_runtime.h>

#define NV   8
#define C_CH 32
#define H_F  128
#define W_F  128
#define RESO 64

#define VOXEL_F ((float)(0.3/64.0))
#define HALF_F  ((float)(0.3/128.0))

// Scratch: transposed features (NV,H,W,C) and mask-sum over i per (v,j,k)
__device__ __align__(16) float g_featsT[NV * H_F * W_F * C_CH];
__device__ float g_msum[NV * RESO * RESO];

// ---------------------------------------------------------------------------
// Kernel A: transpose feats (NV,C,H,W) -> (NV,H,W,C) so a bilinear tap reads
// 32 contiguous floats (8x LDG.128) instead of 32 strided scalars.
// ---------------------------------------------------------------------------
__global__ void transpose_kernel(const float* __restrict__ feats) {
    __shared__ float tile[32][33];
    int v = blockIdx.z, y = blockIdx.y, xb = blockIdx.x * 32;
    int tx = threadIdx.x, ty = threadIdx.y;  // ty = channel, tx = x
    tile[ty][tx] = feats[((v * C_CH + ty) * H_F + y) * W_F + xb + tx];
    __syncthreads();
    // now tx = channel, ty = x
    g_featsT[((v * H_F + y) * W_F + xb + ty) * C_CH + tx] = tile[tx][ty];
}

// ---------------------------------------------------------------------------
// Kernel B: msum[v][j][k] = sum over i of mask(v,i,j,k)
// (reference normalizes mask over axis=1 which is the i/x axis)
// ---------------------------------------------------------------------------
__global__ void msum_kernel(const float* __restrict__ Ks,
                            const float* __restrict__ poses,
                            const float* __restrict__ bbox,
                            const int* __restrict__ ph,
                            const int* __restrict__ pw) {
    int idx = blockIdx.x * blockDim.x + threadIdx.x;  // 8*64*64 = 32768
    int k = idx & 63, j = (idx >> 6) & 63, v = idx >> 12;

    // M = K @ [R|t]  (top-3 rows of K_pad @ pose_h)
    const float* K = Ks + v * 9;
    const float* P = poses + v * 12;
    float M[12];
#pragma unroll
    for (int r = 0; r < 3; r++)
#pragma unroll
        for (int c = 0; c < 4; c++)
            M[r * 4 + c] = K[r * 3 + 0] * P[0 * 4 + c] +
                           K[r * 3 + 1] * P[1 * 4 + c] +
                           K[r * 3 + 2] * P[2 * 4 + c];

    float img_wf = (float)(*pw), img_hf = (float)(*ph);
    float y = (float)j * VOXEL_F + HALF_F + bbox[1];
    float z = (float)k * VOXEL_F + HALF_F + bbox[2];

    float s = 0.f;
    for (int i = 0; i < RESO; i++) {
        float x  = (float)i * VOXEL_F + HALF_F + bbox[0];
        float px = M[0] * x + M[1] * y + M[2]  * z + M[3];
        float py = M[4] * x + M[5] * y + M[6]  * z + M[7];
        float pz = M[8] * x + M[9] * y + M[10] * z + M[11];
        float u  = px / pz, vv = py / pz;
        float gx = u / img_wf - 1.f, gy = vv / img_hf - 1.f;
        float ix = (gx + 1.f) * 0.5f * (float)(W_F - 1);
        float iy = (gy + 1.f) * 0.5f * (float)(H_F - 1);
        float m = (ix >= 0.f && ix <= (float)(W_F - 1) &&
                   iy >= 0.f && iy <= (float)(H_F - 1) && pz > 0.f) ? 1.f : 0.f;
        s += m;
    }
    g_msum[idx] = s;  // idx = v*4096 + j*64 + k
}

// ---------------------------------------------------------------------------
// Kernel C: main fused kernel.
// Block = 256 threads = 8 warps. warp w -> view w; lane -> voxel i = bx*32+lane.
// (j,k) fixed per block => iy warp-uniform, ix varies ~0.33px/lane => taps
// nearly identical across the warp (L1-friendly, near-broadcast).
// ---------------------------------------------------------------------------
__global__ __launch_bounds__(256, 2)
void fv_main(const float* __restrict__ Ks,
             const float* __restrict__ poses,
             const float* __restrict__ bbox,
             const int* __restrict__ ph,
             const int* __restrict__ pw,
             const float* __restrict__ W1, const float* __restrict__ b1,
             const float* __restrict__ W2, const float* __restrict__ b2,
             const float* __restrict__ W3, const float* __restrict__ b3,
             float* __restrict__ out) {
    __shared__ __align__(16) float sW1[32 * 32];
    __shared__ __align__(16) float sW2[32 * 16];
    __shared__ __align__(16) float sW3[16 * 8];
    __shared__ __align__(16) float sB1[32];
    __shared__ __align__(16) float sB2[16];
    __shared__ __align__(16) float sB3[8];
    __shared__ float sM[NV * 12];
    __shared__ float s_comp[8 * NV * 32];  // [ch][view][vox] - conflict free both ways
    __shared__ float s_w[NV * 32];         // [view][vox]

    int tid = threadIdx.x;
    for (int t = tid; t < 1024; t += 256) sW1[t] = W1[t];
    for (int t = tid; t < 512; t += 256) sW2[t] = W2[t];
    if (tid < 128) sW3[tid] = W3[tid];
    if (tid < 32)  sB1[tid] = b1[tid];
    if (tid < 16)  sB2[tid] = b2[tid];
    if (tid < 8)   sB3[tid] = b3[tid];
    if (tid < 96) {
        int v = tid / 12, e = tid % 12, r = e >> 2, c = e & 3;
        const float* K = Ks + v * 9;
        const float* P = poses + v * 12;
        sM[tid] = K[r * 3 + 0] * P[0 + c] + K[r * 3 + 1] * P[4 + c] + K[r * 3 + 2] * P[8 + c];
    }
    __syncthreads();

    int v   = tid >> 5;
    int vox = tid & 31;
    int i = blockIdx.x * 32 + vox;
    int j = blockIdx.y;
    int k = blockIdx.z;

    float x = (float)i * VOXEL_F + HALF_F + bbox[0];
    float y = (float)j * VOXEL_F + HALF_F + bbox[1];
    float z = (float)k * VOXEL_F + HALF_F + bbox[2];

    const float* M = sM + v * 12;
    float px = M[0] * x + M[1] * y + M[2]  * z + M[3];
    float py = M[4] * x + M[5] * y + M[6]  * z + M[7];
    float pz = M[8] * x + M[9] * y + M[10] * z + M[11];

    float img_wf = (float)(*pw), img_hf = (float)(*ph);
    float u  = px / pz, vv = py / pz;
    float gx = u / img_wf - 1.f, gy = vv / img_hf - 1.f;
    float ix = (gx + 1.f) * 0.5f * (float)(W_F - 1);
    float iy = (gy + 1.f) * 0.5f * (float)(H_F - 1);

    float ix0 = floorf(ix), iy0 = floorf(iy);
    float ax = ix - ix0, ay = iy - iy0;
    float wnw = (1.f - ax) * (1.f - ay);
    float wne = ax * (1.f - ay);
    float wsw = (1.f - ax) * ay;
    float wse = ax * ay;
    float mask = (ix >= 0.f && ix <= (float)(W_F - 1) &&
                  iy >= 0.f && iy <= (float)(H_F - 1) && pz > 0.f) ? 1.f : 0.f;

    int cx0 = (int)fminf(fmaxf(ix0,       0.f), (float)(W_F - 1));
    int cx1 = (int)fminf(fmaxf(ix0 + 1.f, 0.f), (float)(W_F - 1));
    int cy0 = (int)fminf(fmaxf(iy0,       0.f), (float)(H_F - 1));
    int cy1 = (int)fminf(fmaxf(iy0 + 1.f, 0.f), (float)(H_F - 1));

    const float4* f00 = (const float4*)(g_featsT + (size_t)((v * H_F + cy0) * W_F + cx0) * C_CH);
    const float4* f01 = (const float4*)(g_featsT + (size_t)((v * H_F + cy0) * W_F + cx1) * C_CH);
    const float4* f10 = (const float4*)(g_featsT + (size_t)((v * H_F + cy1) * W_F + cx0) * C_CH);
    const float4* f11 = (const float4*)(g_featsT + (size_t)((v * H_F + cy1) * W_F + cx1) * C_CH);

    // ---- Layer 1: bilinear sample fused into 32x32 matvec ----
    float acc[32];
#pragma unroll
    for (int q = 0; q < 32; q++) acc[q] = sB1[q];

#pragma unroll
    for (int c4 = 0; c4 < 8; c4++) {
        float4 a = f00[c4], b = f01[c4], c = f10[c4], d = f11[c4];
        float f0 = wnw * a.x + wne * b.x + wsw * c.x + wse * d.x;
        float f1 = wnw * a.y + wne * b.y + wsw * c.y + wse * d.y;
        float f2 = wnw * a.z + wne * b.z + wsw * c.z + wse * d.z;
        float f3 = wnw * a.w + wne * b.w + wsw * c.w + wse * d.w;
        float fq[4] = {f0, f1, f2, f3};
#pragma unroll
        for (int q = 0; q < 4; q++) {
            const float4* wr = (const float4*)(sW1 + (c4 * 4 + q) * 32);
            float fval = fq[q];
#pragma unroll
            for (int j4 = 0; j4 < 8; j4++) {
                float4 ww = wr[j4];
                acc[j4 * 4 + 0] += fval * ww.x;
                acc[j4 * 4 + 1] += fval * ww.y;
                acc[j4 * 4 + 2] += fval * ww.z;
                acc[j4 * 4 + 3] += fval * ww.w;
            }
        }
    }

    // ---- Layer 2: relu(h1) @ W2 (32->16) ----
    float acc2[16];
#pragma unroll
    for (int q = 0; q < 16; q++) acc2[q] = sB2[q];
#pragma unroll
    for (int c = 0; c < 32; c++) {
        float f = fmaxf(acc[c], 0.f);
        const float4* wr = (const float4*)(sW2 + c * 16);
#pragma unroll
        for (int j4 = 0; j4 < 4; j4++) {
            float4 ww = wr[j4];
            acc2[j4 * 4 + 0] += f * ww.x;
            acc2[j4 * 4 + 1] += f * ww.y;
            acc2[j4 * 4 + 2] += f * ww.z;
            acc2[j4 * 4 + 3] += f * ww.w;
        }
    }

    // ---- Layer 3: relu(h2) @ W3 (16->8) ----
    float comp[8];
#pragma unroll
    for (int q = 0; q < 8; q++) comp[q] = sB3[q];
#pragma unroll
    for (int c = 0; c < 16; c++) {
        float f = fmaxf(acc2[c], 0.f);
        const float4* wr = (const float4*)(sW3 + c * 8);
        float4 w0 = wr[0], w1 = wr[1];
        comp[0] += f * w0.x; comp[1] += f * w0.y;
        comp[2] += f * w0.z; comp[3] += f * w0.w;
        comp[4] += f * w1.x; comp[5] += f * w1.y;
        comp[6] += f * w1.z; comp[7] += f * w1.w;
    }

    float S = g_msum[v * (RESO * RESO) + j * RESO + k];
    float w = mask / (S + 1e-8f);

    s_w[v * 32 + vox] = w;
#pragma unroll
    for (int ch = 0; ch < 8; ch++)
        s_comp[(ch * NV + v) * 32 + vox] = comp[ch];

    __syncthreads();

    // ---- Reduction across views: mean then variance ----
    int vox2 = tid & 31;
    int ch   = tid >> 5;  // 0..7
    float mean = 0.f;
#pragma unroll
    for (int v2 = 0; v2 < NV; v2++)
        mean += s_w[v2 * 32 + vox2] * s_comp[(ch * NV + v2) * 32 + vox2];
    float var = 0.f;
#pragma unroll
    for (int v2 = 0; v2 < NV; v2++) {
        float d = s_comp[(ch * NV + v2) * 32 + vox2] - mean;
        var += s_w[v2 * 32 + vox2] * d * d;
    }

    int i_out = blockIdx.x * 32 + vox2;
    // out[0, c, k, j, i], c in [0,16): mean at c=ch, var at c=ch+8
    out[(( ch      * RESO + k) * RESO + j) * RESO + i_out] = mean;
    out[(((ch + 8) * RESO + k) * RESO + j) * RESO + i_out] = var;
}

// ---------------------------------------------------------------------------
extern "C" void kernel_launch(void* const* d_in, const int* in_sizes, int n_in,
                              void* d_out, int out_size) {
    const float* feats = (const float*)d_in[0];
    const float* poses = (const float*)d_in[1];
    const float* Ks    = (const float*)d_in[2];
    const float* bbox  = (const float*)d_in[3];
    const int*   ph    = (const int*)d_in[4];
    const int*   pw    = (const int*)d_in[5];
    const float* W1 = (const float*)d_in[6];
    const float* b1 = (const float*)d_in[7];
    const float* W2 = (const float*)d_in[8];
    const float* b2 = (const float*)d_in[9];
    const float* W3 = (const float*)d_in[10];
    const float* b3 = (const float*)d_in[11];
    float* out = (float*)d_out;

    dim3 tb(32, 32);
    dim3 tg(W_F / 32, H_F, NV);
    transpose_kernel<<<tg, tb>>>(feats);

    msum_kernel<<<(NV * RESO * RESO) / 256, 256>>>(Ks, poses, bbox, ph, pw);

    dim3 mg(RESO / 32, RESO, RESO);
    fv_main<<<mg, 256>>>(Ks, poses, bbox, ph, pw, W1, b1, W2, b2, W3, b3, out);
}

// round 2
// speedup vs baseline: 1.5274x; 1.5274x over previous
#include <cuda_runtime.h>

#define NV   8
#define C_CH 32
#define H_F  128
#define W_F  128
#define HW_F (H_F * W_F)
#define RESO 64

#define VOXEL_F ((float)(0.3/64.0))
#define HALF_F  ((float)(0.3/128.0))

// Scratch: G[v,y,x,c'] = feats[v,:,y,x] @ W1 + b1   (layer-1 hoisted through bilinear)
__device__ __align__(16) float g_G[NV * HW_F * C_CH];
__device__ float g_msum[NV * RESO * RESO];

// ---------------------------------------------------------------------------
// Kernel A: per-pixel GEMM  G = feats @ W1 + b1.
// Thread = 1 pixel; channel loads are coalesced across lanes (consecutive
// pixels), W1 broadcast from smem. Output layout channel-contiguous for the
// sampler's LDG.128.
// ---------------------------------------------------------------------------
__global__ __launch_bounds__(256)
void g_gemm_kernel(const float* __restrict__ feats,
                   const float* __restrict__ W1,
                   const float* __restrict__ b1) {
    __shared__ __align__(16) float sW1[C_CH * C_CH];
    __shared__ float sB1[C_CH];
    int tid = threadIdx.x;
    for (int t = tid; t < 1024; t += 256) sW1[t] = W1[t];
    if (tid < 32) sB1[tid] = b1[tid];
    __syncthreads();

    int p  = blockIdx.x * 256 + tid;     // 0 .. NV*HW-1
    int v  = p >> 14;                    // / 16384
    int pl = p & (HW_F - 1);
    const float* fp = feats + (size_t)v * C_CH * HW_F + pl;

    float acc[32];
#pragma unroll
    for (int q = 0; q < 32; q++) acc[q] = sB1[q];

#pragma unroll
    for (int c = 0; c < 32; c++) {
        float f = fp[c * HW_F];
        const float4* wr = (const float4*)(sW1 + c * 32);
#pragma unroll
        for (int j4 = 0; j4 < 8; j4++) {
            float4 w = wr[j4];
            acc[j4 * 4 + 0] += f * w.x;
            acc[j4 * 4 + 1] += f * w.y;
            acc[j4 * 4 + 2] += f * w.z;
            acc[j4 * 4 + 3] += f * w.w;
        }
    }

    float4* gp = (float4*)(g_G + (size_t)p * 32);
#pragma unroll
    for (int j4 = 0; j4 < 8; j4++)
        gp[j4] = make_float4(acc[j4 * 4 + 0], acc[j4 * 4 + 1],
                             acc[j4 * 4 + 2], acc[j4 * 4 + 3]);
}

// ---------------------------------------------------------------------------
// Kernel B: msum[v][j][k] = sum over i of mask(v,i,j,k)
// ---------------------------------------------------------------------------
__global__ void msum_kernel(const float* __restrict__ Ks,
                            const float* __restrict__ poses,
                            const float* __restrict__ bbox,
                            const int* __restrict__ ph,
                            const int* __restrict__ pw) {
    int idx = blockIdx.x * blockDim.x + threadIdx.x;  // 8*64*64 = 32768
    int k = idx & 63, j = (idx >> 6) & 63, v = idx >> 12;

    const float* K = Ks + v * 9;
    const float* P = poses + v * 12;
    float M[12];
#pragma unroll
    for (int r = 0; r < 3; r++)
#pragma unroll
        for (int c = 0; c < 4; c++)
            M[r * 4 + c] = K[r * 3 + 0] * P[0 * 4 + c] +
                           K[r * 3 + 1] * P[1 * 4 + c] +
                           K[r * 3 + 2] * P[2 * 4 + c];

    float img_wf = (float)(*pw), img_hf = (float)(*ph);
    float y = (float)j * VOXEL_F + HALF_F + bbox[1];
    float z = (float)k * VOXEL_F + HALF_F + bbox[2];

    float s = 0.f;
    for (int i = 0; i < RESO; i++) {
        float x  = (float)i * VOXEL_F + HALF_F + bbox[0];
        float px = M[0] * x + M[1] * y + M[2]  * z + M[3];
        float py = M[4] * x + M[5] * y + M[6]  * z + M[7];
        float pz = M[8] * x + M[9] * y + M[10] * z + M[11];
        float u  = px / pz, vv = py / pz;
        float gx = u / img_wf - 1.f, gy = vv / img_hf - 1.f;
        float ix = (gx + 1.f) * 0.5f * (float)(W_F - 1);
        float iy = (gy + 1.f) * 0.5f * (float)(H_F - 1);
        float m = (ix >= 0.f && ix <= (float)(W_F - 1) &&
                   iy >= 0.f && iy <= (float)(H_F - 1) && pz > 0.f) ? 1.f : 0.f;
        s += m;
    }
    g_msum[idx] = s;
}

// ---------------------------------------------------------------------------
// Kernel C: main fused kernel (sample G, ReLU, W2, W3, weighted mean/var).
// Block = 256 threads = 8 warps. warp w -> view w; lane -> voxel i.
// ---------------------------------------------------------------------------
__global__ __launch_bounds__(256, 3)
void fv_main(const float* __restrict__ Ks,
             const float* __restrict__ poses,
             const float* __restrict__ bbox,
             const int* __restrict__ ph,
             const int* __restrict__ pw,
             const float* __restrict__ W2, const float* __restrict__ b2,
             const float* __restrict__ W3, const float* __restrict__ b3,
             float* __restrict__ out) {
    __shared__ __align__(16) float sW2[32 * 16];
    __shared__ __align__(16) float sW3[16 * 8];
    __shared__ __align__(16) float sB2[16];
    __shared__ __align__(16) float sB3[8];
    __shared__ float sM[NV * 12];
    __shared__ float s_comp[8 * NV * 32];  // [ch][view][vox]
    __shared__ float s_w[NV * 32];         // [view][vox]

    int tid = threadIdx.x;
    for (int t = tid; t < 512; t += 256) sW2[t] = W2[t];
    if (tid < 128) sW3[tid] = W3[tid];
    if (tid < 16)  sB2[tid] = b2[tid];
    if (tid < 8)   sB3[tid] = b3[tid];
    if (tid < 96) {
        int v = tid / 12, e = tid % 12, r = e >> 2, c = e & 3;
        const float* K = Ks + v * 9;
        const float* P = poses + v * 12;
        sM[tid] = K[r * 3 + 0] * P[0 + c] + K[r * 3 + 1] * P[4 + c] + K[r * 3 + 2] * P[8 + c];
    }
    __syncthreads();

    int v   = tid >> 5;
    int vox = tid & 31;
    int i = blockIdx.x * 32 + vox;
    int j = blockIdx.y;
    int k = blockIdx.z;

    float x = (float)i * VOXEL_F + HALF_F + bbox[0];
    float y = (float)j * VOXEL_F + HALF_F + bbox[1];
    float z = (float)k * VOXEL_F + HALF_F + bbox[2];

    const float* M = sM + v * 12;
    float px = M[0] * x + M[1] * y + M[2]  * z + M[3];
    float py = M[4] * x + M[5] * y + M[6]  * z + M[7];
    float pz = M[8] * x + M[9] * y + M[10] * z + M[11];

    float img_wf = (float)(*pw), img_hf = (float)(*ph);
    float u  = px / pz, vv = py / pz;
    float gx = u / img_wf - 1.f, gy = vv / img_hf - 1.f;
    float ix = (gx + 1.f) * 0.5f * (float)(W_F - 1);
    float iy = (gy + 1.f) * 0.5f * (float)(H_F - 1);

    float ix0 = floorf(ix), iy0 = floorf(iy);
    float ax = ix - ix0, ay = iy - iy0;
    float wnw = (1.f - ax) * (1.f - ay);
    float wne = ax * (1.f - ay);
    float wsw = (1.f - ax) * ay;
    float wse = ax * ay;
    float mask = (ix >= 0.f && ix <= (float)(W_F - 1) &&
                  iy >= 0.f && iy <= (float)(H_F - 1) && pz > 0.f) ? 1.f : 0.f;

    int cx0 = (int)fminf(fmaxf(ix0,       0.f), (float)(W_F - 1));
    int cx1 = (int)fminf(fmaxf(ix0 + 1.f, 0.f), (float)(W_F - 1));
    int cy0 = (int)fminf(fmaxf(iy0,       0.f), (float)(H_F - 1));
    int cy1 = (int)fminf(fmaxf(iy0 + 1.f, 0.f), (float)(H_F - 1));

    const float4* f00 = (const float4*)(g_G + (size_t)((v * H_F + cy0) * W_F + cx0) * C_CH);
    const float4* f01 = (const float4*)(g_G + (size_t)((v * H_F + cy0) * W_F + cx1) * C_CH);
    const float4* f10 = (const float4*)(g_G + (size_t)((v * H_F + cy1) * W_F + cx0) * C_CH);
    const float4* f11 = (const float4*)(g_G + (size_t)((v * H_F + cy1) * W_F + cx1) * C_CH);

    // ---- bilinear sample of G (== h1 pre-ReLU), fused into layer 2 ----
    float acc2[16];
#pragma unroll
    for (int q = 0; q < 16; q++) acc2[q] = sB2[q];

#pragma unroll
    for (int c4 = 0; c4 < 8; c4++) {
        float4 a = f00[c4], b = f01[c4], c = f10[c4], d = f11[c4];
        float fq[4];
        fq[0] = wnw * a.x + wne * b.x + wsw * c.x + wse * d.x;
        fq[1] = wnw * a.y + wne * b.y + wsw * c.y + wse * d.y;
        fq[2] = wnw * a.z + wne * b.z + wsw * c.z + wse * d.z;
        fq[3] = wnw * a.w + wne * b.w + wsw * c.w + wse * d.w;
#pragma unroll
        for (int q = 0; q < 4; q++) {
            float h = fmaxf(fq[q], 0.f);
            const float4* wr = (const float4*)(sW2 + (c4 * 4 + q) * 16);
#pragma unroll
            for (int j4 = 0; j4 < 4; j4++) {
                float4 ww = wr[j4];
                acc2[j4 * 4 + 0] += h * ww.x;
                acc2[j4 * 4 + 1] += h * ww.y;
                acc2[j4 * 4 + 2] += h * ww.z;
                acc2[j4 * 4 + 3] += h * ww.w;
            }
        }
    }

    // ---- Layer 3: relu(h2) @ W3 (16->8) ----
    float comp[8];
#pragma unroll
    for (int q = 0; q < 8; q++) comp[q] = sB3[q];
#pragma unroll
    for (int c = 0; c < 16; c++) {
        float f = fmaxf(acc2[c], 0.f);
        const float4* wr = (const float4*)(sW3 + c * 8);
        float4 w0 = wr[0], w1 = wr[1];
        comp[0] += f * w0.x; comp[1] += f * w0.y;
        comp[2] += f * w0.z; comp[3] += f * w0.w;
        comp[4] += f * w1.x; comp[5] += f * w1.y;
        comp[6] += f * w1.z; comp[7] += f * w1.w;
    }

    float S = g_msum[v * (RESO * RESO) + j * RESO + k];
    float w = mask / (S + 1e-8f);

    s_w[v * 32 + vox] = w;
#pragma unroll
    for (int ch = 0; ch < 8; ch++)
        s_comp[(ch * NV + v) * 32 + vox] = comp[ch];

    __syncthreads();

    // ---- Reduction across views: mean then variance ----
    int vox2 = tid & 31;
    int ch   = tid >> 5;  // 0..7
    float mean = 0.f;
#pragma unroll
    for (int v2 = 0; v2 < NV; v2++)
        mean += s_w[v2 * 32 + vox2] * s_comp[(ch * NV + v2) * 32 + vox2];
    float var = 0.f;
#pragma unroll
    for (int v2 = 0; v2 < NV; v2++) {
        float d = s_comp[(ch * NV + v2) * 32 + vox2] - mean;
        var += s_w[v2 * 32 + vox2] * d * d;
    }

    int i_out = blockIdx.x * 32 + vox2;
    out[(( ch      * RESO + k) * RESO + j) * RESO + i_out] = mean;
    out[(((ch + 8) * RESO + k) * RESO + j) * RESO + i_out] = var;
}

// ---------------------------------------------------------------------------
extern "C" void kernel_launch(void* const* d_in, const int* in_sizes, int n_in,
                              void* d_out, int out_size) {
    const float* feats = (const float*)d_in[0];
    const float* poses = (const float*)d_in[1];
    const float* Ks    = (const float*)d_in[2];
    const float* bbox  = (const float*)d_in[3];
    const int*   ph    = (const int*)d_in[4];
    const int*   pw    = (const int*)d_in[5];
    const float* W1 = (const float*)d_in[6];
    const float* b1 = (const float*)d_in[7];
    const float* W2 = (const float*)d_in[8];
    const float* b2 = (const float*)d_in[9];
    const float* W3 = (const float*)d_in[10];
    const float* b3 = (const float*)d_in[11];
    float* out = (float*)d_out;

    g_gemm_kernel<<<(NV * HW_F) / 256, 256>>>(feats, W1, b1);

    msum_kernel<<<(NV * RESO * RESO) / 256, 256>>>(Ks, poses, bbox, ph, pw);

    dim3 mg(RESO / 32, RESO, RESO);
    fv_main<<<mg, 256>>>(Ks, poses, bbox, ph, pw, W2, b2, W3, b3, out);
}

// round 3
// speedup vs baseline: 1.5511x; 1.0155x over previous
#include <cuda_runtime.h>

#define NV   8
#define C_CH 32
#define H_F  128
#define W_F  128
#define HW_F (H_F * W_F)
#define RESO 64

#define VOXEL_F ((float)(0.3/64.0))
#define HALF_F  ((float)(0.3/128.0))

typedef unsigned long long u64;

// ---- packed f32x2 helpers (FFMA2: 2 IEEE fp32 FMAs per issue slot) ----
__device__ __forceinline__ u64 pack2(float lo, float hi) {
    u64 r; asm("mov.b64 %0, {%1, %2};" : "=l"(r) : "f"(lo), "f"(hi)); return r;
}
__device__ __forceinline__ float2 unpack2(u64 p) {
    float2 r; asm("mov.b64 {%0, %1}, %2;" : "=f"(r.x), "=f"(r.y) : "l"(p)); return r;
}
__device__ __forceinline__ void ffma2(u64& d, u64 a, u64 b) {
    asm("fma.rn.f32x2 %0, %1, %2, %0;" : "+l"(d) : "l"(a), "l"(b));
}
__device__ __forceinline__ u64 fmul2(u64 a, u64 b) {
    u64 d; asm("mul.rn.f32x2 %0, %1, %2;" : "=l"(d) : "l"(a), "l"(b)); return d;
}

// Scratch: G[v,y,x,c'] = feats[v,:,y,x] @ W1 + b1   (layer-1 hoisted through bilinear)
__device__ __align__(16) float g_G[NV * HW_F * C_CH];
__device__ float g_msum[NV * RESO * RESO];

// ---------------------------------------------------------------------------
// Kernel A: per-pixel GEMM  G = feats @ W1 + b1 (packed f32x2 accumulators).
// ---------------------------------------------------------------------------
__global__ __launch_bounds__(256)
void g_gemm_kernel(const float* __restrict__ feats,
                   const float* __restrict__ W1,
                   const float* __restrict__ b1) {
    __shared__ __align__(16) float sW1[C_CH * C_CH];
    __shared__ __align__(16) float sB1[C_CH];
    int tid = threadIdx.x;
    for (int t = tid; t < 1024; t += 256) sW1[t] = W1[t];
    if (tid < 32) sB1[tid] = b1[tid];
    __syncthreads();

    int p  = blockIdx.x * 256 + tid;     // 0 .. NV*HW-1
    int v  = p >> 14;                    // / 16384
    int pl = p & (HW_F - 1);
    const float* fp = feats + (size_t)v * C_CH * HW_F + pl;

    u64 acc[16];
    const u64* sB1p = (const u64*)sB1;
#pragma unroll
    for (int q = 0; q < 16; q++) acc[q] = sB1p[q];

#pragma unroll
    for (int c = 0; c < 32; c++) {
        float f = fp[c * HW_F];
        u64 f2 = pack2(f, f);
        const ulonglong2* wr = (const ulonglong2*)(sW1 + c * 32);  // 8x LDS.128
#pragma unroll
        for (int j4 = 0; j4 < 8; j4++) {
            ulonglong2 w = wr[j4];
            ffma2(acc[j4 * 2 + 0], f2, w.x);
            ffma2(acc[j4 * 2 + 1], f2, w.y);
        }
    }

    ulonglong2* gp = (ulonglong2*)(g_G + (size_t)p * 32);
#pragma unroll
    for (int j4 = 0; j4 < 8; j4++) {
        ulonglong2 o; o.x = acc[j4 * 2 + 0]; o.y = acc[j4 * 2 + 1];
        gp[j4] = o;
    }
}

// ---------------------------------------------------------------------------
// Kernel B: msum[v][j][k] = sum over i of mask(v,i,j,k)
// ---------------------------------------------------------------------------
__global__ void msum_kernel(const float* __restrict__ Ks,
                            const float* __restrict__ poses,
                            const float* __restrict__ bbox,
                            const int* __restrict__ ph,
                            const int* __restrict__ pw) {
    int idx = blockIdx.x * blockDim.x + threadIdx.x;  // 8*64*64 = 32768
    int k = idx & 63, j = (idx >> 6) & 63, v = idx >> 12;

    const float* K = Ks + v * 9;
    const float* P = poses + v * 12;
    float M[12];
#pragma unroll
    for (int r = 0; r < 3; r++)
#pragma unroll
        for (int c = 0; c < 4; c++)
            M[r * 4 + c] = K[r * 3 + 0] * P[0 * 4 + c] +
                           K[r * 3 + 1] * P[1 * 4 + c] +
                           K[r * 3 + 2] * P[2 * 4 + c];

    float img_wf = (float)(*pw), img_hf = (float)(*ph);
    float y = (float)j * VOXEL_F + HALF_F + bbox[1];
    float z = (float)k * VOXEL_F + HALF_F + bbox[2];

    float s = 0.f;
    for (int i = 0; i < RESO; i++) {
        float x  = (float)i * VOXEL_F + HALF_F + bbox[0];
        float px = M[0] * x + M[1] * y + M[2]  * z + M[3];
        float py = M[4] * x + M[5] * y + M[6]  * z + M[7];
        float pz = M[8] * x + M[9] * y + M[10] * z + M[11];
        float u  = px / pz, vv = py / pz;
        float gx = u / img_wf - 1.f, gy = vv / img_hf - 1.f;
        float ix = (gx + 1.f) * 0.5f * (float)(W_F - 1);
        float iy = (gy + 1.f) * 0.5f * (float)(H_F - 1);
        float m = (ix >= 0.f && ix <= (float)(W_F - 1) &&
                   iy >= 0.f && iy <= (float)(H_F - 1) && pz > 0.f) ? 1.f : 0.f;
        s += m;
    }
    g_msum[idx] = s;
}

// ---------------------------------------------------------------------------
// Kernel C: main fused kernel, packed f32x2 math.
// Block = 256 threads = 8 warps. warp w -> view w; lane -> voxel i.
// ---------------------------------------------------------------------------
__global__ __launch_bounds__(256, 3)
void fv_main(const float* __restrict__ Ks,
             const float* __restrict__ poses,
             const float* __restrict__ bbox,
             const int* __restrict__ ph,
             const int* __restrict__ pw,
             const float* __restrict__ W2, const float* __restrict__ b2,
             const float* __restrict__ W3, const float* __restrict__ b3,
             float* __restrict__ out) {
    __shared__ __align__(16) float sW2[32 * 16];
    __shared__ __align__(16) float sW3[16 * 8];
    __shared__ __align__(16) float sB2[16];
    __shared__ __align__(16) float sB3[8];
    __shared__ float sM[NV * 12];
    __shared__ float s_comp[8 * NV * 32];  // [ch][view][vox]
    __shared__ float s_w[NV * 32];         // [view][vox]

    int tid = threadIdx.x;
    for (int t = tid; t < 512; t += 256) sW2[t] = W2[t];
    if (tid < 128) sW3[tid] = W3[tid];
    if (tid < 16)  sB2[tid] = b2[tid];
    if (tid < 8)   sB3[tid] = b3[tid];
    if (tid < 96) {
        int v = tid / 12, e = tid % 12, r = e >> 2, c = e & 3;
        const float* K = Ks + v * 9;
        const float* P = poses + v * 12;
        sM[tid] = K[r * 3 + 0] * P[0 + c] + K[r * 3 + 1] * P[4 + c] + K[r * 3 + 2] * P[8 + c];
    }
    __syncthreads();

    int v   = tid >> 5;
    int vox = tid & 31;
    int i = blockIdx.x * 32 + vox;
    int j = blockIdx.y;
    int k = blockIdx.z;

    float x = (float)i * VOXEL_F + HALF_F + bbox[0];
    float y = (float)j * VOXEL_F + HALF_F + bbox[1];
    float z = (float)k * VOXEL_F + HALF_F + bbox[2];

    const float* M = sM + v * 12;
    float px = M[0] * x + M[1] * y + M[2]  * z + M[3];
    float py = M[4] * x + M[5] * y + M[6]  * z + M[7];
    float pz = M[8] * x + M[9] * y + M[10] * z + M[11];

    float img_wf = (float)(*pw), img_hf = (float)(*ph);
    float u  = px / pz, vv = py / pz;
    float gx = u / img_wf - 1.f, gy = vv / img_hf - 1.f;
    float ix = (gx + 1.f) * 0.5f * (float)(W_F - 1);
    float iy = (gy + 1.f) * 0.5f * (float)(H_F - 1);

    float ix0 = floorf(ix), iy0 = floorf(iy);
    float ax = ix - ix0, ay = iy - iy0;
    float wnw = (1.f - ax) * (1.f - ay);
    float wne = ax * (1.f - ay);
    float wsw = (1.f - ax) * ay;
    float wse = ax * ay;
    float mask = (ix >= 0.f && ix <= (float)(W_F - 1) &&
                  iy >= 0.f && iy <= (float)(H_F - 1) && pz > 0.f) ? 1.f : 0.f;

    int cx0 = (int)fminf(fmaxf(ix0,       0.f), (float)(W_F - 1));
    int cx1 = (int)fminf(fmaxf(ix0 + 1.f, 0.f), (float)(W_F - 1));
    int cy0 = (int)fminf(fmaxf(iy0,       0.f), (float)(H_F - 1));
    int cy1 = (int)fminf(fmaxf(iy0 + 1.f, 0.f), (float)(H_F - 1));

    const ulonglong2* f00 = (const ulonglong2*)(g_G + (size_t)((v * H_F + cy0) * W_F + cx0) * C_CH);
    const ulonglong2* f01 = (const ulonglong2*)(g_G + (size_t)((v * H_F + cy0) * W_F + cx1) * C_CH);
    const ulonglong2* f10 = (const ulonglong2*)(g_G + (size_t)((v * H_F + cy1) * W_F + cx0) * C_CH);
    const ulonglong2* f11 = (const ulonglong2*)(g_G + (size_t)((v * H_F + cy1) * W_F + cx1) * C_CH);

    u64 wnw2 = pack2(wnw, wnw);
    u64 wne2 = pack2(wne, wne);
    u64 wsw2 = pack2(wsw, wsw);
    u64 wse2 = pack2(wse, wse);

    // ---- bilinear sample of G (== h1 pre-ReLU) fused into layer 2, packed ----
    u64 acc2[8];  // 16 outputs as 8 f32x2
    const u64* sB2p = (const u64*)sB2;
#pragma unroll
    for (int q = 0; q < 8; q++) acc2[q] = sB2p[q];

#pragma unroll
    for (int c4 = 0; c4 < 8; c4++) {
        ulonglong2 a = f00[c4], b = f01[c4], c = f10[c4], d = f11[c4];
        u64 fp0 = fmul2(wnw2, a.x); ffma2(fp0, wne2, b.x); ffma2(fp0, wsw2, c.x); ffma2(fp0, wse2, d.x);
        u64 fp1 = fmul2(wnw2, a.y); ffma2(fp1, wne2, b.y); ffma2(fp1, wsw2, c.y); ffma2(fp1, wse2, d.y);
        float2 t0 = unpack2(fp0), t1 = unpack2(fp1);
        float h[4] = { fmaxf(t0.x, 0.f), fmaxf(t0.y, 0.f),
                       fmaxf(t1.x, 0.f), fmaxf(t1.y, 0.f) };
#pragma unroll
        for (int q = 0; q < 4; q++) {
            u64 h2 = pack2(h[q], h[q]);
            const ulonglong2* wr = (const ulonglong2*)(sW2 + (c4 * 4 + q) * 16);  // 4x LDS.128
#pragma unroll
            for (int j4 = 0; j4 < 4; j4++) {
                ulonglong2 ww = wr[j4];
                ffma2(acc2[j4 * 2 + 0], h2, ww.x);
                ffma2(acc2[j4 * 2 + 1], h2, ww.y);
            }
        }
    }

    // ---- Layer 3: relu(h2) @ W3 (16->8), packed ----
    u64 compp[4];
    const u64* sB3p = (const u64*)sB3;
#pragma unroll
    for (int q = 0; q < 4; q++) compp[q] = sB3p[q];

#pragma unroll
    for (int p = 0; p < 8; p++) {
        float2 t = unpack2(acc2[p]);
        float h0 = fmaxf(t.x, 0.f), h1 = fmaxf(t.y, 0.f);
#pragma unroll
        for (int half = 0; half < 2; half++) {
            float hh = half ? h1 : h0;
            int c = p * 2 + half;
            u64 h2 = pack2(hh, hh);
            const ulonglong2* wr = (const ulonglong2*)(sW3 + c * 8);  // 2x LDS.128
            ulonglong2 w0 = wr[0], w1 = wr[1];
            ffma2(compp[0], h2, w0.x);
            ffma2(compp[1], h2, w0.y);
            ffma2(compp[2], h2, w1.x);
            ffma2(compp[3], h2, w1.y);
        }
    }

    float S = g_msum[v * (RESO * RESO) + j * RESO + k];
    float w = mask / (S + 1e-8f);

    s_w[v * 32 + vox] = w;
#pragma unroll
    for (int p = 0; p < 4; p++) {
        float2 t = unpack2(compp[p]);
        s_comp[((p * 2 + 0) * NV + v) * 32 + vox] = t.x;
        s_comp[((p * 2 + 1) * NV + v) * 32 + vox] = t.y;
    }

    __syncthreads();

    // ---- Reduction across views: mean then variance ----
    int vox2 = tid & 31;
    int ch   = tid >> 5;  // 0..7
    float mean = 0.f;
#pragma unroll
    for (int v2 = 0; v2 < NV; v2++)
        mean += s_w[v2 * 32 + vox2] * s_comp[(ch * NV + v2) * 32 + vox2];
    float var = 0.f;
#pragma unroll
    for (int v2 = 0; v2 < NV; v2++) {
        float d = s_comp[(ch * NV + v2) * 32 + vox2] - mean;
        var += s_w[v2 * 32 + vox2] * d * d;
    }

    int i_out = blockIdx.x * 32 + vox2;
    out[(( ch      * RESO + k) * RESO + j) * RESO + i_out] = mean;
    out[(((ch + 8) * RESO + k) * RESO + j) * RESO + i_out] = var;
}

// ---------------------------------------------------------------------------
extern "C" void kernel_launch(void* const* d_in, const int* in_sizes, int n_in,
                              void* d_out, int out_size) {
    const float* feats = (const float*)d_in[0];
    const float* poses = (const float*)d_in[1];
    const float* Ks    = (const float*)d_in[2];
    const float* bbox  = (const float*)d_in[3];
    const int*   ph    = (const int*)d_in[4];
    const int*   pw    = (const int*)d_in[5];
    const float* W1 = (const float*)d_in[6];
    const float* b1 = (const float*)d_in[7];
    const float* W2 = (const float*)d_in[8];
    const float* b2 = (const float*)d_in[9];
    const float* W3 = (const float*)d_in[10];
    const float* b3 = (const float*)d_in[11];
    float* out = (float*)d_out;

    g_gemm_kernel<<<(NV * HW_F) / 256, 256>>>(feats, W1, b1);

    msum_kernel<<<(NV * RESO * RESO) / 256, 256>>>(Ks, poses, bbox, ph, pw);

    dim3 mg(RESO / 32, RESO, RESO);
    fv_main<<<mg, 256>>>(Ks, poses, bbox, ph, pw, W2, b2, W3, b3, out);
}

// round 4
// speedup vs baseline: 2.1867x; 1.4098x over previous
#include <cuda_runtime.h>

#define NV   8
#define C_CH 32
#define H_F  128
#define W_F  128
#define HW_F (H_F * W_F)
#define RESO 64

#define VOXEL_F ((float)(0.3/64.0))
#define HALF_F  ((float)(0.3/128.0))

typedef unsigned long long u64;

// ---- packed f32x2 helpers (FFMA2: 2 IEEE fp32 FMAs per issue slot) ----
__device__ __forceinline__ u64 pack2(float lo, float hi) {
    u64 r; asm("mov.b64 %0, {%1, %2};" : "=l"(r) : "f"(lo), "f"(hi)); return r;
}
__device__ __forceinline__ float2 unpack2(u64 p) {
    float2 r; asm("mov.b64 {%0, %1}, %2;" : "=f"(r.x), "=f"(r.y) : "l"(p)); return r;
}
__device__ __forceinline__ void ffma2(u64& d, u64 a, u64 b) {
    asm("fma.rn.f32x2 %0, %1, %2, %0;" : "+l"(d) : "l"(a), "l"(b));
}
__device__ __forceinline__ u64 fmul2(u64 a, u64 b) {
    u64 d; asm("mul.rn.f32x2 %0, %1, %2;" : "=l"(d) : "l"(a), "l"(b)); return d;
}

// Scratch: plane-split G. G2[c4][(v*H+y)*W+x] = float4 of channels 4*c4..4*c4+3
// of feats[v,:,y,x] @ W1 + b1. Plane-split => gather lanes are 16B/pixel apart
// => ~2 cache lines per warp-gather instead of ~11.
__device__ __align__(16) float g_G2[8 * NV * HW_F * 4];
__device__ float g_msum[NV * RESO * RESO];

// ---------------------------------------------------------------------------
// Kernel A: per-pixel GEMM  G = feats @ W1 + b1 (packed f32x2 accumulators),
// written to plane-split layout.
// ---------------------------------------------------------------------------
__global__ __launch_bounds__(256)
void g_gemm_kernel(const float* __restrict__ feats,
                   const float* __restrict__ W1,
                   const float* __restrict__ b1) {
    __shared__ __align__(16) float sW1[C_CH * C_CH];
    __shared__ __align__(16) float sB1[C_CH];
    int tid = threadIdx.x;
    for (int t = tid; t < 1024; t += 256) sW1[t] = W1[t];
    if (tid < 32) sB1[tid] = b1[tid];
    __syncthreads();

    int p  = blockIdx.x * 256 + tid;     // 0 .. NV*HW-1
    int v  = p >> 14;                    // / 16384
    int pl = p & (HW_F - 1);
    const float* fp = feats + (size_t)v * C_CH * HW_F + pl;

    u64 acc[16];
    const u64* sB1p = (const u64*)sB1;
#pragma unroll
    for (int q = 0; q < 16; q++) acc[q] = sB1p[q];

#pragma unroll
    for (int c = 0; c < 32; c++) {
        float f = fp[c * HW_F];
        u64 f2 = pack2(f, f);
        const ulonglong2* wr = (const ulonglong2*)(sW1 + c * 32);  // 8x LDS.128
#pragma unroll
        for (int j4 = 0; j4 < 8; j4++) {
            ulonglong2 w = wr[j4];
            ffma2(acc[j4 * 2 + 0], f2, w.x);
            ffma2(acc[j4 * 2 + 1], f2, w.y);
        }
    }

    // plane-split store: plane c4 holds float4 for channels 4c4..4c4+3
    ulonglong2* gbase = (ulonglong2*)g_G2;
#pragma unroll
    for (int c4 = 0; c4 < 8; c4++) {
        ulonglong2 o; o.x = acc[c4 * 2 + 0]; o.y = acc[c4 * 2 + 1];
        gbase[(size_t)c4 * (NV * HW_F) + p] = o;
    }
}

// ---------------------------------------------------------------------------
// Kernel B: msum[v][j][k] = sum over i of mask(v,i,j,k)
// ---------------------------------------------------------------------------
__global__ void msum_kernel(const float* __restrict__ Ks,
                            const float* __restrict__ poses,
                            const float* __restrict__ bbox,
                            const int* __restrict__ ph,
                            const int* __restrict__ pw) {
    int idx = blockIdx.x * blockDim.x + threadIdx.x;  // 8*64*64 = 32768
    int k = idx & 63, j = (idx >> 6) & 63, v = idx >> 12;

    const float* K = Ks + v * 9;
    const float* P = poses + v * 12;
    float M[12];
#pragma unroll
    for (int r = 0; r < 3; r++)
#pragma unroll
        for (int c = 0; c < 4; c++)
            M[r * 4 + c] = K[r * 3 + 0] * P[0 * 4 + c] +
                           K[r * 3 + 1] * P[1 * 4 + c] +
                           K[r * 3 + 2] * P[2 * 4 + c];

    float img_wf = (float)(*pw), img_hf = (float)(*ph);
    float y = (float)j * VOXEL_F + HALF_F + bbox[1];
    float z = (float)k * VOXEL_F + HALF_F + bbox[2];

    float s = 0.f;
    for (int i = 0; i < RESO; i++) {
        float x  = (float)i * VOXEL_F + HALF_F + bbox[0];
        float px = M[0] * x + M[1] * y + M[2]  * z + M[3];
        float py = M[4] * x + M[5] * y + M[6]  * z + M[7];
        float pz = M[8] * x + M[9] * y + M[10] * z + M[11];
        float u  = px / pz, vv = py / pz;
        float gx = u / img_wf - 1.f, gy = vv / img_hf - 1.f;
        float ix = (gx + 1.f) * 0.5f * (float)(W_F - 1);
        float iy = (gy + 1.f) * 0.5f * (float)(H_F - 1);
        float m = (ix >= 0.f && ix <= (float)(W_F - 1) &&
                   iy >= 0.f && iy <= (float)(H_F - 1) && pz > 0.f) ? 1.f : 0.f;
        s += m;
    }
    g_msum[idx] = s;
}

// ---------------------------------------------------------------------------
// Kernel C: main fused kernel, packed f32x2 math + plane-split gathers.
// Block = 256 threads = 8 warps. warp w -> view w; lane -> voxel i.
// ---------------------------------------------------------------------------
__global__ __launch_bounds__(256, 3)
void fv_main(const float* __restrict__ Ks,
             const float* __restrict__ poses,
             const float* __restrict__ bbox,
             const int* __restrict__ ph,
             const int* __restrict__ pw,
             const float* __restrict__ W2, const float* __restrict__ b2,
             const float* __restrict__ W3, const float* __restrict__ b3,
             float* __restrict__ out) {
    __shared__ __align__(16) float sW2[32 * 16];
    __shared__ __align__(16) float sW3[16 * 8];
    __shared__ __align__(16) float sB2[16];
    __shared__ __align__(16) float sB3[8];
    __shared__ float sM[NV * 12];
    __shared__ float s_comp[8 * NV * 32];  // [ch][view][vox]
    __shared__ float s_w[NV * 32];         // [view][vox]

    int tid = threadIdx.x;
    for (int t = tid; t < 512; t += 256) sW2[t] = W2[t];
    if (tid < 128) sW3[tid] = W3[tid];
    if (tid < 16)  sB2[tid] = b2[tid];
    if (tid < 8)   sB3[tid] = b3[tid];
    if (tid < 96) {
        int v = tid / 12, e = tid % 12, r = e >> 2, c = e & 3;
        const float* K = Ks + v * 9;
        const float* P = poses + v * 12;
        sM[tid] = K[r * 3 + 0] * P[0 + c] + K[r * 3 + 1] * P[4 + c] + K[r * 3 + 2] * P[8 + c];
    }
    __syncthreads();

    int v   = tid >> 5;
    int vox = tid & 31;
    int i = blockIdx.x * 32 + vox;
    int j = blockIdx.y;
    int k = blockIdx.z;

    float x = (float)i * VOXEL_F + HALF_F + bbox[0];
    float y = (float)j * VOXEL_F + HALF_F + bbox[1];
    float z = (float)k * VOXEL_F + HALF_F + bbox[2];

    const float* M = sM + v * 12;
    float px = M[0] * x + M[1] * y + M[2]  * z + M[3];
    float py = M[4] * x + M[5] * y + M[6]  * z + M[7];
    float pz = M[8] * x + M[9] * y + M[10] * z + M[11];

    float img_wf = (float)(*pw), img_hf = (float)(*ph);
    float u  = px / pz, vv = py / pz;
    float gx = u / img_wf - 1.f, gy = vv / img_hf - 1.f;
    float ix = (gx + 1.f) * 0.5f * (float)(W_F - 1);
    float iy = (gy + 1.f) * 0.5f * (float)(H_F - 1);

    float ix0 = floorf(ix), iy0 = floorf(iy);
    float ax = ix - ix0, ay = iy - iy0;
    float wnw = (1.f - ax) * (1.f - ay);
    float wne = ax * (1.f - ay);
    float wsw = (1.f - ax) * ay;
    float wse = ax * ay;
    float mask = (ix >= 0.f && ix <= (float)(W_F - 1) &&
                  iy >= 0.f && iy <= (float)(H_F - 1) && pz > 0.f) ? 1.f : 0.f;

    int cx0 = (int)fminf(fmaxf(ix0,       0.f), (float)(W_F - 1));
    int cx1 = (int)fminf(fmaxf(ix0 + 1.f, 0.f), (float)(W_F - 1));
    int cy0 = (int)fminf(fmaxf(iy0,       0.f), (float)(H_F - 1));
    int cy1 = (int)fminf(fmaxf(iy0 + 1.f, 0.f), (float)(H_F - 1));

    int p00 = (v * H_F + cy0) * W_F + cx0;
    int p01 = (v * H_F + cy0) * W_F + cx1;
    int p10 = (v * H_F + cy1) * W_F + cx0;
    int p11 = (v * H_F + cy1) * W_F + cx1;

    u64 wnw2 = pack2(wnw, wnw);
    u64 wne2 = pack2(wne, wne);
    u64 wsw2 = pack2(wsw, wsw);
    u64 wse2 = pack2(wse, wse);

    // ---- bilinear sample of plane-split G fused into layer 2, packed ----
    u64 acc2[8];  // 16 outputs as 8 f32x2
    const u64* sB2p = (const u64*)sB2;
#pragma unroll
    for (int q = 0; q < 8; q++) acc2[q] = sB2p[q];

    const ulonglong2* gbase = (const ulonglong2*)g_G2;
#pragma unroll
    for (int c4 = 0; c4 < 8; c4++) {
        const ulonglong2* plane = gbase + (size_t)c4 * (NV * HW_F);
        ulonglong2 a = plane[p00], b = plane[p01], c = plane[p10], d = plane[p11];
        u64 fp0 = fmul2(wnw2, a.x); ffma2(fp0, wne2, b.x); ffma2(fp0, wsw2, c.x); ffma2(fp0, wse2, d.x);
        u64 fp1 = fmul2(wnw2, a.y); ffma2(fp1, wne2, b.y); ffma2(fp1, wsw2, c.y); ffma2(fp1, wse2, d.y);
        float2 t0 = unpack2(fp0), t1 = unpack2(fp1);
        float h[4] = { fmaxf(t0.x, 0.f), fmaxf(t0.y, 0.f),
                       fmaxf(t1.x, 0.f), fmaxf(t1.y, 0.f) };
#pragma unroll
        for (int q = 0; q < 4; q++) {
            u64 h2 = pack2(h[q], h[q]);
            const ulonglong2* wr = (const ulonglong2*)(sW2 + (c4 * 4 + q) * 16);  // 4x LDS.128
#pragma unroll
            for (int j4 = 0; j4 < 4; j4++) {
                ulonglong2 ww = wr[j4];
                ffma2(acc2[j4 * 2 + 0], h2, ww.x);
                ffma2(acc2[j4 * 2 + 1], h2, ww.y);
            }
        }
    }

    // ---- Layer 3: relu(h2) @ W3 (16->8), packed ----
    u64 compp[4];
    const u64* sB3p = (const u64*)sB3;
#pragma unroll
    for (int q = 0; q < 4; q++) compp[q] = sB3p[q];

#pragma unroll
    for (int p = 0; p < 8; p++) {
        float2 t = unpack2(acc2[p]);
        float h0 = fmaxf(t.x, 0.f), h1 = fmaxf(t.y, 0.f);
#pragma unroll
        for (int half = 0; half < 2; half++) {
            float hh = half ? h1 : h0;
            int c = p * 2 + half;
            u64 h2 = pack2(hh, hh);
            const ulonglong2* wr = (const ulonglong2*)(sW3 + c * 8);  // 2x LDS.128
            ulonglong2 w0 = wr[0], w1 = wr[1];
            ffma2(compp[0], h2, w0.x);
            ffma2(compp[1], h2, w0.y);
            ffma2(compp[2], h2, w1.x);
            ffma2(compp[3], h2, w1.y);
        }
    }

    float S = g_msum[v * (RESO * RESO) + j * RESO + k];
    float w = mask / (S + 1e-8f);

    s_w[v * 32 + vox] = w;
#pragma unroll
    for (int p = 0; p < 4; p++) {
        float2 t = unpack2(compp[p]);
        s_comp[((p * 2 + 0) * NV + v) * 32 + vox] = t.x;
        s_comp[((p * 2 + 1) * NV + v) * 32 + vox] = t.y;
    }

    __syncthreads();

    // ---- Reduction across views: mean then variance ----
    int vox2 = tid & 31;
    int ch   = tid >> 5;  // 0..7
    float mean = 0.f;
#pragma unroll
    for (int v2 = 0; v2 < NV; v2++)
        mean += s_w[v2 * 32 + vox2] * s_comp[(ch * NV + v2) * 32 + vox2];
    float var = 0.f;
#pragma unroll
    for (int v2 = 0; v2 < NV; v2++) {
        float d = s_comp[(ch * NV + v2) * 32 + vox2] - mean;
        var += s_w[v2 * 32 + vox2] * d * d;
    }

    int i_out = blockIdx.x * 32 + vox2;
    out[(( ch      * RESO + k) * RESO + j) * RESO + i_out] = mean;
    out[(((ch + 8) * RESO + k) * RESO + j) * RESO + i_out] = var;
}

// ---------------------------------------------------------------------------
extern "C" void kernel_launch(void* const* d_in, const int* in_sizes, int n_in,
                              void* d_out, int out_size) {
    const float* feats = (const float*)d_in[0];
    const float* poses = (const float*)d_in[1];
    const float* Ks    = (const float*)d_in[2];
    const float* bbox  = (const float*)d_in[3];
    const int*   ph    = (const int*)d_in[4];
    const int*   pw    = (const int*)d_in[5];
    const float* W1 = (const float*)d_in[6];
    const float* b1 = (const float*)d_in[7];
    const float* W2 = (const float*)d_in[8];
    const float* b2 = (const float*)d_in[9];
    const float* W3 = (const float*)d_in[10];
    const float* b3 = (const float*)d_in[11];
    float* out = (float*)d_out;

    g_gemm_kernel<<<(NV * HW_F) / 256, 256>>>(feats, W1, b1);

    msum_kernel<<<(NV * RESO * RESO) / 256, 256>>>(Ks, poses, bbox, ph, pw);

    dim3 mg(RESO / 32, RESO, RESO);
    fv_main<<<mg, 256>>>(Ks, poses, bbox, ph, pw, W2, b2, W3, b3, out);
}

// round 5
// speedup vs baseline: 2.4239x; 1.1085x over previous
#include <cuda_runtime.h>
#include <cuda_fp16.h>

#define NV   8
#define C_CH 32
#define H_F  128
#define W_F  128
#define HW_F (H_F * W_F)
#define RESO 64

#define VOXEL_F ((float)(0.3/64.0))
#define HALF_F  ((float)(0.3/128.0))

typedef unsigned long long u64;

// ---- packed f32x2 helpers (FFMA2: 2 IEEE fp32 FMAs per issue slot) ----
__device__ __forceinline__ u64 pack2(float lo, float hi) {
    u64 r; asm("mov.b64 %0, {%1, %2};" : "=l"(r) : "f"(lo), "f"(hi)); return r;
}
__device__ __forceinline__ float2 unpack2(u64 p) {
    float2 r; asm("mov.b64 {%0, %1}, %2;" : "=f"(r.x), "=f"(r.y) : "l"(p)); return r;
}
__device__ __forceinline__ void ffma2(u64& d, u64 a, u64 b) {
    asm("fma.rn.f32x2 %0, %1, %2, %0;" : "+l"(d) : "l"(a), "l"(b));
}
__device__ __forceinline__ unsigned f32x2_to_f16x2(u64 p) {
    float2 t = unpack2(p);
    unsigned r;  // hi = t.y (channel 2q+1), lo = t.x (channel 2q)
    asm("cvt.rn.f16x2.f32 %0, %1, %2;" : "=r"(r) : "f"(t.y), "f"(t.x));
    return r;
}

// Scratch: fp16 plane-split G. Plane p (of 4) holds channels 8p..8p+7 as
// 4x half2 = 16B per pixel.  G values feed interp+ReLU; fp16 rounding ~2.4e-4.
__device__ __align__(16) unsigned g_Gh[4 * NV * HW_F * 4];  // uint4 per pixel per plane
__device__ float g_msum[NV * RESO * RESO];

// ---------------------------------------------------------------------------
// Kernel A: per-pixel GEMM  G = feats @ W1 + b1 (fp32 math, fp16 store).
// ---------------------------------------------------------------------------
__global__ __launch_bounds__(256)
void g_gemm_kernel(const float* __restrict__ feats,
                   const float* __restrict__ W1,
                   const float* __restrict__ b1) {
    __shared__ __align__(16) float sW1[C_CH * C_CH];
    __shared__ __align__(16) float sB1[C_CH];
    int tid = threadIdx.x;
    for (int t = tid; t < 1024; t += 256) sW1[t] = W1[t];
    if (tid < 32) sB1[tid] = b1[tid];
    __syncthreads();

    int p  = blockIdx.x * 256 + tid;     // 0 .. NV*HW-1
    int v  = p >> 14;
    int pl = p & (HW_F - 1);
    const float* fp = feats + (size_t)v * C_CH * HW_F + pl;

    u64 acc[16];
    const u64* sB1p = (const u64*)sB1;
#pragma unroll
    for (int q = 0; q < 16; q++) acc[q] = sB1p[q];

#pragma unroll
    for (int c = 0; c < 32; c++) {
        float f = fp[c * HW_F];
        u64 f2 = pack2(f, f);
        const ulonglong2* wr = (const ulonglong2*)(sW1 + c * 32);
#pragma unroll
        for (int j4 = 0; j4 < 8; j4++) {
            ulonglong2 w = wr[j4];
            ffma2(acc[j4 * 2 + 0], f2, w.x);
            ffma2(acc[j4 * 2 + 1], f2, w.y);
        }
    }

    uint4* gbase = (uint4*)g_Gh;
#pragma unroll
    for (int pp = 0; pp < 4; pp++) {
        uint4 o;
        o.x = f32x2_to_f16x2(acc[pp * 4 + 0]);
        o.y = f32x2_to_f16x2(acc[pp * 4 + 1]);
        o.z = f32x2_to_f16x2(acc[pp * 4 + 2]);
        o.w = f32x2_to_f16x2(acc[pp * 4 + 3]);
        gbase[(size_t)pp * (NV * HW_F) + p] = o;
    }
}

// ---------------------------------------------------------------------------
// Kernel B: msum[v][j][k] = sum over i of mask(v,i,j,k)   (exact fp32)
// ---------------------------------------------------------------------------
__global__ void msum_kernel(const float* __restrict__ Ks,
                            const float* __restrict__ poses,
                            const float* __restrict__ bbox,
                            const int* __restrict__ ph,
                            const int* __restrict__ pw) {
    int idx = blockIdx.x * blockDim.x + threadIdx.x;
    int k = idx & 63, j = (idx >> 6) & 63, v = idx >> 12;

    const float* K = Ks + v * 9;
    const float* P = poses + v * 12;
    float M[12];
#pragma unroll
    for (int r = 0; r < 3; r++)
#pragma unroll
        for (int c = 0; c < 4; c++)
            M[r * 4 + c] = K[r * 3 + 0] * P[0 * 4 + c] +
                           K[r * 3 + 1] * P[1 * 4 + c] +
                           K[r * 3 + 2] * P[2 * 4 + c];

    float img_wf = (float)(*pw), img_hf = (float)(*ph);
    float y = (float)j * VOXEL_F + HALF_F + bbox[1];
    float z = (float)k * VOXEL_F + HALF_F + bbox[2];

    float s = 0.f;
    for (int i = 0; i < RESO; i++) {
        float x  = (float)i * VOXEL_F + HALF_F + bbox[0];
        float px = M[0] * x + M[1] * y + M[2]  * z + M[3];
        float py = M[4] * x + M[5] * y + M[6]  * z + M[7];
        float pz = M[8] * x + M[9] * y + M[10] * z + M[11];
        float u  = px / pz, vv = py / pz;
        float gx = u / img_wf - 1.f, gy = vv / img_hf - 1.f;
        float ix = (gx + 1.f) * 0.5f * (float)(W_F - 1);
        float iy = (gy + 1.f) * 0.5f * (float)(H_F - 1);
        float m = (ix >= 0.f && ix <= (float)(W_F - 1) &&
                   iy >= 0.f && iy <= (float)(H_F - 1) && pz > 0.f) ? 1.f : 0.f;
        s += m;
    }
    g_msum[idx] = s;
}

// ---------------------------------------------------------------------------
// Kernel C: main fused kernel. fp16 gathers + half2 interp/ReLU, fp32 MLP.
// Block = 256 threads = 8 warps. warp w -> view w; lane -> voxel i.
// ---------------------------------------------------------------------------
__global__ __launch_bounds__(256, 3)
void fv_main(const float* __restrict__ Ks,
             const float* __restrict__ poses,
             const float* __restrict__ bbox,
             const int* __restrict__ ph,
             const int* __restrict__ pw,
             const float* __restrict__ W2, const float* __restrict__ b2,
             const float* __restrict__ W3, const float* __restrict__ b3,
             float* __restrict__ out) {
    __shared__ __align__(16) float sW2[32 * 16];
    __shared__ __align__(16) float sW3[16 * 8];
    __shared__ __align__(16) float sB2[16];
    __shared__ __align__(16) float sB3[8];
    __shared__ float sM[NV * 12];
    __shared__ float s_comp[8 * NV * 32];  // [ch][view][vox]
    __shared__ float s_w[NV * 32];         // [view][vox]

    int tid = threadIdx.x;
    for (int t = tid; t < 512; t += 256) sW2[t] = W2[t];
    if (tid < 128) sW3[tid] = W3[tid];
    if (tid < 16)  sB2[tid] = b2[tid];
    if (tid < 8)   sB3[tid] = b3[tid];
    if (tid < 96) {
        int v = tid / 12, e = tid % 12, r = e >> 2, c = e & 3;
        const float* K = Ks + v * 9;
        const float* P = poses + v * 12;
        sM[tid] = K[r * 3 + 0] * P[0 + c] + K[r * 3 + 1] * P[4 + c] + K[r * 3 + 2] * P[8 + c];
    }
    __syncthreads();

    int v   = tid >> 5;
    int vox = tid & 31;
    int i = blockIdx.x * 32 + vox;
    int j = blockIdx.y;
    int k = blockIdx.z;

    float x = (float)i * VOXEL_F + HALF_F + bbox[0];
    float y = (float)j * VOXEL_F + HALF_F + bbox[1];
    float z = (float)k * VOXEL_F + HALF_F + bbox[2];

    const float* M = sM + v * 12;
    float px = M[0] * x + M[1] * y + M[2]  * z + M[3];
    float py = M[4] * x + M[5] * y + M[6]  * z + M[7];
    float pz = M[8] * x + M[9] * y + M[10] * z + M[11];

    float img_wf = (float)(*pw), img_hf = (float)(*ph);
    float u  = px / pz, vv = py / pz;
    float gx = u / img_wf - 1.f, gy = vv / img_hf - 1.f;
    float ix = (gx + 1.f) * 0.5f * (float)(W_F - 1);
    float iy = (gy + 1.f) * 0.5f * (float)(H_F - 1);

    float ix0 = floorf(ix), iy0 = floorf(iy);
    float ax = ix - ix0, ay = iy - iy0;
    float wnw = (1.f - ax) * (1.f - ay);
    float wne = ax * (1.f - ay);
    float wsw = (1.f - ax) * ay;
    float wse = ax * ay;
    float mask = (ix >= 0.f && ix <= (float)(W_F - 1) &&
                  iy >= 0.f && iy <= (float)(H_F - 1) && pz > 0.f) ? 1.f : 0.f;

    int cx0 = (int)fminf(fmaxf(ix0,       0.f), (float)(W_F - 1));
    int cx1 = (int)fminf(fmaxf(ix0 + 1.f, 0.f), (float)(W_F - 1));
    int cy0 = (int)fminf(fmaxf(iy0,       0.f), (float)(H_F - 1));
    int cy1 = (int)fminf(fmaxf(iy0 + 1.f, 0.f), (float)(H_F - 1));

    int p00 = (v * H_F + cy0) * W_F + cx0;
    int p01 = (v * H_F + cy0) * W_F + cx1;
    int p10 = (v * H_F + cy1) * W_F + cx0;
    int p11 = (v * H_F + cy1) * W_F + cx1;

    __half2 wnwh = __float2half2_rn(wnw);
    __half2 wneh = __float2half2_rn(wne);
    __half2 wswh = __float2half2_rn(wsw);
    __half2 wseh = __float2half2_rn(wse);
    __half2 zeroh = __float2half2_rn(0.f);

    u64 acc2[8];  // 16 layer-2 outputs as 8 f32x2
    const u64* sB2p = (const u64*)sB2;
#pragma unroll
    for (int q = 0; q < 8; q++) acc2[q] = sB2p[q];

    const uint4* gbase = (const uint4*)g_Gh;
#pragma unroll
    for (int pp = 0; pp < 4; pp++) {
        const uint4* plane = gbase + (size_t)pp * (NV * HW_F);
        uint4 a = plane[p00], b = plane[p01], c = plane[p10], d = plane[p11];
        const unsigned* au = &a.x; const unsigned* bu = &b.x;
        const unsigned* cu = &c.x; const unsigned* du = &d.x;
#pragma unroll
        for (int q = 0; q < 4; q++) {   // q-th half2 = channels (8pp+2q, 8pp+2q+1)
            __half2 ha = *(const __half2*)&au[q];
            __half2 hb = *(const __half2*)&bu[q];
            __half2 hc = *(const __half2*)&cu[q];
            __half2 hd = *(const __half2*)&du[q];
            __half2 r = __hmul2(wnwh, ha);
            r = __hfma2(wneh, hb, r);
            r = __hfma2(wswh, hc, r);
            r = __hfma2(wseh, hd, r);
            r = __hmax2(r, zeroh);               // ReLU (h1)
            float2 hf = __half22float2(r);
            int c0 = pp * 8 + q * 2;
            u64 h20 = pack2(hf.x, hf.x);
            u64 h21 = pack2(hf.y, hf.y);
            const ulonglong2* wr0 = (const ulonglong2*)(sW2 + (c0    ) * 16);
            const ulonglong2* wr1 = (const ulonglong2*)(sW2 + (c0 + 1) * 16);
#pragma unroll
            for (int j4 = 0; j4 < 4; j4++) {
                ulonglong2 w0 = wr0[j4];
                ffma2(acc2[j4 * 2 + 0], h20, w0.x);
                ffma2(acc2[j4 * 2 + 1], h20, w0.y);
            }
#pragma unroll
            for (int j4 = 0; j4 < 4; j4++) {
                ulonglong2 w1 = wr1[j4];
                ffma2(acc2[j4 * 2 + 0], h21, w1.x);
                ffma2(acc2[j4 * 2 + 1], h21, w1.y);
            }
        }
    }

    // ---- Layer 3: relu(h2) @ W3 (16->8), packed fp32 ----
    u64 compp[4];
    const u64* sB3p = (const u64*)sB3;
#pragma unroll
    for (int q = 0; q < 4; q++) compp[q] = sB3p[q];

#pragma unroll
    for (int p = 0; p < 8; p++) {
        float2 t = unpack2(acc2[p]);
        float h0 = fmaxf(t.x, 0.f), h1 = fmaxf(t.y, 0.f);
#pragma unroll
        for (int half = 0; half < 2; half++) {
            float hh = half ? h1 : h0;
            int c = p * 2 + half;
            u64 h2 = pack2(hh, hh);
            const ulonglong2* wr = (const ulonglong2*)(sW3 + c * 8);
            ulonglong2 w0 = wr[0], w1 = wr[1];
            ffma2(compp[0], h2, w0.x);
            ffma2(compp[1], h2, w0.y);
            ffma2(compp[2], h2, w1.x);
            ffma2(compp[3], h2, w1.y);
        }
    }

    float S = g_msum[v * (RESO * RESO) + j * RESO + k];
    float w = mask / (S + 1e-8f);

    s_w[v * 32 + vox] = w;
#pragma unroll
    for (int p = 0; p < 4; p++) {
        float2 t = unpack2(compp[p]);
        s_comp[((p * 2 + 0) * NV + v) * 32 + vox] = t.x;
        s_comp[((p * 2 + 1) * NV + v) * 32 + vox] = t.y;
    }

    __syncthreads();

    // ---- Reduction across views: mean then variance ----
    int vox2 = tid & 31;
    int ch   = tid >> 5;  // 0..7
    float mean = 0.f;
#pragma unroll
    for (int v2 = 0; v2 < NV; v2++)
        mean += s_w[v2 * 32 + vox2] * s_comp[(ch * NV + v2) * 32 + vox2];
    float var = 0.f;
#pragma unroll
    for (int v2 = 0; v2 < NV; v2++) {
        float d = s_comp[(ch * NV + v2) * 32 + vox2] - mean;
        var += s_w[v2 * 32 + vox2] * d * d;
    }

    int i_out = blockIdx.x * 32 + vox2;
    out[(( ch      * RESO + k) * RESO + j) * RESO + i_out] = mean;
    out[(((ch + 8) * RESO + k) * RESO + j) * RESO + i_out] = var;
}

// ---------------------------------------------------------------------------
extern "C" void kernel_launch(void* const* d_in, const int* in_sizes, int n_in,
                              void* d_out, int out_size) {
    const float* feats = (const float*)d_in[0];
    const float* poses = (const float*)d_in[1];
    const float* Ks    = (const float*)d_in[2];
    const float* bbox  = (const float*)d_in[3];
    const int*   ph    = (const int*)d_in[4];
    const int*   pw    = (const int*)d_in[5];
    const float* W1 = (const float*)d_in[6];
    const float* b1 = (const float*)d_in[7];
    const float* W2 = (const float*)d_in[8];
    const float* b2 = (const float*)d_in[9];
    const float* W3 = (const float*)d_in[10];
    const float* b3 = (const float*)d_in[11];
    float* out = (float*)d_out;

    g_gemm_kernel<<<(NV * HW_F) / 256, 256>>>(feats, W1, b1);

    msum_kernel<<<(NV * RESO * RESO) / 256, 256>>>(Ks, poses, bbox, ph, pw);

    dim3 mg(RESO / 32, RESO, RESO);
    fv_main<<<mg, 256>>>(Ks, poses, bbox, ph, pw, W2, b2, W3, b3, out);
}

// round 6
// speedup vs baseline: 3.3656x; 1.3885x over previous
#include <cuda_runtime.h>
#include <cuda_fp16.h>

#define NV   8
#define C_CH 32
#define H_F  128
#define W_F  128
#define HW_F (H_F * W_F)
#define RESO 64

#define VOXEL_F ((float)(0.3/64.0))
#define HALF_F  ((float)(0.3/128.0))

typedef unsigned long long u64;
typedef unsigned u32;

// ---- packed f32x2 helpers ----
__device__ __forceinline__ u64 pack2(float lo, float hi) {
    u64 r; asm("mov.b64 %0, {%1, %2};" : "=l"(r) : "f"(lo), "f"(hi)); return r;
}
__device__ __forceinline__ float2 unpack2(u64 p) {
    float2 r; asm("mov.b64 {%0, %1}, %2;" : "=f"(r.x), "=f"(r.y) : "l"(p)); return r;
}
__device__ __forceinline__ void ffma2(u64& d, u64 a, u64 b) {
    asm("fma.rn.f32x2 %0, %1, %2, %0;" : "+l"(d) : "l"(a), "l"(b));
}
// pack two fp32 -> f16x2 (lo first)
__device__ __forceinline__ u32 pack_h2(float lo, float hi) {
    u32 r; asm("cvt.rn.f16x2.f32 %0, %1, %2;" : "=r"(r) : "f"(hi), "f"(lo)); return r;
}
__device__ __forceinline__ u32 f32x2_to_f16x2(u64 p) {
    float2 t = unpack2(p);
    return pack_h2(t.x, t.y);
}
__device__ __forceinline__ float rhalf(float x) {   // round-trip through fp16
    return __half2float(__float2half_rn(x));
}

// ---- tensor-core helpers ----
__device__ __forceinline__ void ldsm_x4(u32& r0, u32& r1, u32& r2, u32& r3, u32 addr) {
    asm volatile("ldmatrix.sync.aligned.m8n8.x4.shared.b16 {%0,%1,%2,%3}, [%4];"
                 : "=r"(r0), "=r"(r1), "=r"(r2), "=r"(r3) : "r"(addr));
}
__device__ __forceinline__ void mma16816(float* c, const u32* a, u32 b0, u32 b1) {
    asm volatile("mma.sync.aligned.m16n8k16.row.col.f32.f16.f16.f32 "
                 "{%0,%1,%2,%3}, {%4,%5,%6,%7}, {%8,%9}, {%0,%1,%2,%3};"
                 : "+f"(c[0]), "+f"(c[1]), "+f"(c[2]), "+f"(c[3])
                 : "r"(a[0]), "r"(a[1]), "r"(a[2]), "r"(a[3]), "r"(b0), "r"(b1));
}

// Scratch: fp16 plane-split G. Plane p (of 4) holds channels 8p..8p+7 as
// 4x half2 = 16B per pixel.
__device__ __align__(16) u32 g_Gh[4 * NV * HW_F * 4];
__device__ float g_msum[NV * RESO * RESO];

#define GEMM_BLOCKS 512

// ---------------------------------------------------------------------------
// Prep kernel: blocks [0,512) do per-pixel GEMM G = feats@W1+b1 (fp16 store);
// blocks [512,640) compute msum (fills the gemm wave tail).
// ---------------------------------------------------------------------------
__global__ __launch_bounds__(256)
void prep_kernel(const float* __restrict__ feats,
                 const float* __restrict__ W1,
                 const float* __restrict__ b1,
                 const float* __restrict__ Ks,
                 const float* __restrict__ poses,
                 const float* __restrict__ bbox,
                 const int* __restrict__ ph,
                 const int* __restrict__ pw) {
    int tid = threadIdx.x;
    if (blockIdx.x < GEMM_BLOCKS) {
        __shared__ __align__(16) float sW1[C_CH * C_CH];
        __shared__ __align__(16) float sB1[C_CH];
        for (int t = tid; t < 1024; t += 256) sW1[t] = W1[t];
        if (tid < 32) sB1[tid] = b1[tid];
        __syncthreads();

        int p  = blockIdx.x * 256 + tid;
        int v  = p >> 14;
        int pl = p & (HW_F - 1);
        const float* fp = feats + (size_t)v * C_CH * HW_F + pl;

        u64 acc[16];
        const u64* sB1p = (const u64*)sB1;
#pragma unroll
        for (int q = 0; q < 16; q++) acc[q] = sB1p[q];

#pragma unroll
        for (int c = 0; c < 32; c++) {
            float f = fp[c * HW_F];
            u64 f2 = pack2(f, f);
            const ulonglong2* wr = (const ulonglong2*)(sW1 + c * 32);
#pragma unroll
            for (int j4 = 0; j4 < 8; j4++) {
                ulonglong2 w = wr[j4];
                ffma2(acc[j4 * 2 + 0], f2, w.x);
                ffma2(acc[j4 * 2 + 1], f2, w.y);
            }
        }

        uint4* gbase = (uint4*)g_Gh;
#pragma unroll
        for (int pp = 0; pp < 4; pp++) {
            uint4 o;
            o.x = f32x2_to_f16x2(acc[pp * 4 + 0]);
            o.y = f32x2_to_f16x2(acc[pp * 4 + 1]);
            o.z = f32x2_to_f16x2(acc[pp * 4 + 2]);
            o.w = f32x2_to_f16x2(acc[pp * 4 + 3]);
            gbase[(size_t)pp * (NV * HW_F) + p] = o;
        }
    } else {
        int idx = (blockIdx.x - GEMM_BLOCKS) * 256 + tid;   // 0..32767
        int k = idx & 63, j = (idx >> 6) & 63, v = idx >> 12;

        const float* K = Ks + v * 9;
        const float* P = poses + v * 12;
        float M[12];
#pragma unroll
        for (int r = 0; r < 3; r++)
#pragma unroll
            for (int c = 0; c < 4; c++)
                M[r * 4 + c] = K[r * 3 + 0] * P[0 * 4 + c] +
                               K[r * 3 + 1] * P[1 * 4 + c] +
                               K[r * 3 + 2] * P[2 * 4 + c];

        float img_wf = (float)(*pw), img_hf = (float)(*ph);
        float y = (float)j * VOXEL_F + HALF_F + bbox[1];
        float z = (float)k * VOXEL_F + HALF_F + bbox[2];

        float s = 0.f;
        for (int i = 0; i < RESO; i++) {
            float x  = (float)i * VOXEL_F + HALF_F + bbox[0];
            float px = M[0] * x + M[1] * y + M[2]  * z + M[3];
            float py = M[4] * x + M[5] * y + M[6]  * z + M[7];
            float pz = M[8] * x + M[9] * y + M[10] * z + M[11];
            float u  = px / pz, vv = py / pz;
            float gx = u / img_wf - 1.f, gy = vv / img_hf - 1.f;
            float ix = (gx + 1.f) * 0.5f * (float)(W_F - 1);
            float iy = (gy + 1.f) * 0.5f * (float)(H_F - 1);
            float m = (ix >= 0.f && ix <= (float)(W_F - 1) &&
                       iy >= 0.f && iy <= (float)(H_F - 1) && pz > 0.f) ? 1.f : 0.f;
            s += m;
        }
        g_msum[idx] = s;
    }
}

// ---------------------------------------------------------------------------
// Main fused kernel: fp16 gathers + half2 interp/ReLU, then HMMA layers 2+3.
// Block = 256 threads = 8 warps. warp w -> view w; lane -> voxel i.
// ---------------------------------------------------------------------------
#define ROWB 80   // staging row stride (bytes): 64B data + 16B pad, LDSM conflict-free

__global__ __launch_bounds__(256, 3)
void fv_main(const float* __restrict__ Ks,
             const float* __restrict__ poses,
             const float* __restrict__ bbox,
             const int* __restrict__ ph,
             const int* __restrict__ pw,
             const float* __restrict__ W2, const float* __restrict__ b2,
             const float* __restrict__ W3, const float* __restrict__ b3,
             float* __restrict__ out) {
    __shared__ __align__(16) float sW2[32 * 16];
    __shared__ __align__(16) float sW3[16 * 8];
    __shared__ __align__(16) float sB2[16];
    __shared__ __align__(16) float sB3[8];
    __shared__ float sM[NV * 12];
    __shared__ float s_comp[8 * NV * 32];  // [ch][view][vox]
    __shared__ float s_w[NV * 32];         // [view][vox]
    __shared__ __align__(16) unsigned char sA[NV * 32 * ROWB];  // per-warp h1 staging

    int tid = threadIdx.x;
    for (int t = tid; t < 512; t += 256) sW2[t] = W2[t];
    if (tid < 128) sW3[tid] = W3[tid];
    if (tid < 16)  sB2[tid] = b2[tid];
    if (tid < 8)   sB3[tid] = b3[tid];
    if (tid < 96) {
        int v = tid / 12, e = tid % 12, r = e >> 2, c = e & 3;
        const float* K = Ks + v * 9;
        const float* P = poses + v * 12;
        sM[tid] = K[r * 3 + 0] * P[0 + c] + K[r * 3 + 1] * P[4 + c] + K[r * 3 + 2] * P[8 + c];
    }
    __syncthreads();

    int v    = tid >> 5;       // warp = view
    int lane = tid & 31;       // lane = voxel (row)
    int i = blockIdx.x * 32 + lane;
    int j = blockIdx.y;
    int k = blockIdx.z;

    // ---- projection (per-lane voxel) ----
    float x = (float)i * VOXEL_F + HALF_F + bbox[0];
    float y = (float)j * VOXEL_F + HALF_F + bbox[1];
    float z = (float)k * VOXEL_F + HALF_F + bbox[2];

    const float* M = sM + v * 12;
    float px = M[0] * x + M[1] * y + M[2]  * z + M[3];
    float py = M[4] * x + M[5] * y + M[6]  * z + M[7];
    float pz = M[8] * x + M[9] * y + M[10] * z + M[11];

    float img_wf = (float)(*pw), img_hf = (float)(*ph);
    float u  = px / pz, vv = py / pz;
    float gx = u / img_wf - 1.f, gy = vv / img_hf - 1.f;
    float ix = (gx + 1.f) * 0.5f * (float)(W_F - 1);
    float iy = (gy + 1.f) * 0.5f * (float)(H_F - 1);

    float ix0 = floorf(ix), iy0 = floorf(iy);
    float ax = ix - ix0, ay = iy - iy0;
    float wnw = (1.f - ax) * (1.f - ay);
    float wne = ax * (1.f - ay);
    float wsw = (1.f - ax) * ay;
    float wse = ax * ay;
    float mask = (ix >= 0.f && ix <= (float)(W_F - 1) &&
                  iy >= 0.f && iy <= (float)(H_F - 1) && pz > 0.f) ? 1.f : 0.f;

    int cx0 = (int)fminf(fmaxf(ix0,       0.f), (float)(W_F - 1));
    int cx1 = (int)fminf(fmaxf(ix0 + 1.f, 0.f), (float)(W_F - 1));
    int cy0 = (int)fminf(fmaxf(iy0,       0.f), (float)(H_F - 1));
    int cy1 = (int)fminf(fmaxf(iy0 + 1.f, 0.f), (float)(H_F - 1));

    int p00 = (v * H_F + cy0) * W_F + cx0;
    int p01 = (v * H_F + cy0) * W_F + cx1;
    int p10 = (v * H_F + cy1) * W_F + cx0;
    int p11 = (v * H_F + cy1) * W_F + cx1;

    __half2 wnwh = __float2half2_rn(wnw);
    __half2 wneh = __float2half2_rn(wne);
    __half2 wswh = __float2half2_rn(wsw);
    __half2 wseh = __float2half2_rn(wse);
    __half2 zeroh = __float2half2_rn(0.f);

    // ---- gather + interp + ReLU -> h1 row (32ch fp16) into sA staging ----
    unsigned char* myrow = sA + (v * 32 + lane) * ROWB;
    const uint4* gbase = (const uint4*)g_Gh;
#pragma unroll
    for (int pp = 0; pp < 4; pp++) {
        const uint4* plane = gbase + (size_t)pp * (NV * HW_F);
        uint4 a = plane[p00], b = plane[p01], c = plane[p10], d = plane[p11];
        const u32* au = &a.x; const u32* bu = &b.x;
        const u32* cu = &c.x; const u32* du = &d.x;
        u32 hq[4];
#pragma unroll
        for (int q = 0; q < 4; q++) {
            __half2 ha = *(const __half2*)&au[q];
            __half2 hb = *(const __half2*)&bu[q];
            __half2 hc = *(const __half2*)&cu[q];
            __half2 hd = *(const __half2*)&du[q];
            __half2 r = __hmul2(wnwh, ha);
            r = __hfma2(wneh, hb, r);
            r = __hfma2(wswh, hc, r);
            r = __hfma2(wseh, hd, r);
            r = __hmax2(r, zeroh);               // ReLU(h1), fp16
            hq[q] = *(const u32*)&r;
        }
        ((uint4*)myrow)[pp] = make_uint4(hq[0], hq[1], hq[2], hq[3]);
    }

    // ---- build W2/W3 fragments (fp16 hi + lo split => weight error ~0) ----
    int bn = lane >> 2;          // fragment n index 0..7
    int bk = (lane & 3) * 2;     // fragment k base 0,2,4,6

    u32 B2h[2][2][2], B2l[2][2][2];
#pragma unroll
    for (int kt = 0; kt < 2; kt++)
#pragma unroll
        for (int nt = 0; nt < 2; nt++) {
            int n = bn + nt * 8;
            int k0 = bk + kt * 16;
            float w0 = sW2[(k0    ) * 16 + n];
            float w1 = sW2[(k0 + 1) * 16 + n];
            float w8 = sW2[(k0 + 8) * 16 + n];
            float w9 = sW2[(k0 + 9) * 16 + n];
            B2h[kt][nt][0] = pack_h2(w0, w1);
            B2h[kt][nt][1] = pack_h2(w8, w9);
            B2l[kt][nt][0] = pack_h2(w0 - rhalf(w0), w1 - rhalf(w1));
            B2l[kt][nt][1] = pack_h2(w8 - rhalf(w8), w9 - rhalf(w9));
        }
    u32 B3h[2], B3l[2];
    {
        float w0 = sW3[(bk    ) * 8 + bn];
        float w1 = sW3[(bk + 1) * 8 + bn];
        float w8 = sW3[(bk + 8) * 8 + bn];
        float w9 = sW3[(bk + 9) * 8 + bn];
        B3h[0] = pack_h2(w0, w1);
        B3h[1] = pack_h2(w8, w9);
        B3l[0] = pack_h2(w0 - rhalf(w0), w1 - rhalf(w1));
        B3l[1] = pack_h2(w8 - rhalf(w8), w9 - rhalf(w9));
    }

    __syncwarp();

    // ---- load A fragments via ldmatrix ----
    u32 abase = (u32)__cvta_generic_to_shared(sA + v * 32 * ROWB);
    u32 laddr = abase + (lane & 15) * ROWB + ((lane >> 4) << 4);
    u32 A[2][2][4];   // [mtile][ktile][4]
#pragma unroll
    for (int mt = 0; mt < 2; mt++)
#pragma unroll
        for (int kt = 0; kt < 2; kt++)
            ldsm_x4(A[mt][kt][0], A[mt][kt][1], A[mt][kt][2], A[mt][kt][3],
                    laddr + mt * 16 * ROWB + kt * 32);

    // ---- layer 2: C[mt][nt] = h1 @ W2 + b2 (16 HMMA) ----
    float C2[2][2][4];
#pragma unroll
    for (int mt = 0; mt < 2; mt++)
#pragma unroll
        for (int nt = 0; nt < 2; nt++) {
            float bb0 = sB2[nt * 8 + bk];
            float bb1 = sB2[nt * 8 + bk + 1];
            C2[mt][nt][0] = bb0; C2[mt][nt][1] = bb1;
            C2[mt][nt][2] = bb0; C2[mt][nt][3] = bb1;
        }
#pragma unroll
    for (int mt = 0; mt < 2; mt++)
#pragma unroll
        for (int nt = 0; nt < 2; nt++)
#pragma unroll
            for (int kt = 0; kt < 2; kt++) {
                mma16816(C2[mt][nt], A[mt][kt], B2h[kt][nt][0], B2h[kt][nt][1]);
                mma16816(C2[mt][nt], A[mt][kt], B2l[kt][nt][0], B2l[kt][nt][1]);
            }

    // ---- layer 3: comp = relu(h2) @ W3 + b3 (4 HMMA, fragment chaining) ----
    float C3[2][4];
#pragma unroll
    for (int mt = 0; mt < 2; mt++) {
        u32 A3[4];
        A3[0] = pack_h2(fmaxf(C2[mt][0][0], 0.f), fmaxf(C2[mt][0][1], 0.f));
        A3[1] = pack_h2(fmaxf(C2[mt][0][2], 0.f), fmaxf(C2[mt][0][3], 0.f));
        A3[2] = pack_h2(fmaxf(C2[mt][1][0], 0.f), fmaxf(C2[mt][1][1], 0.f));
        A3[3] = pack_h2(fmaxf(C2[mt][1][2], 0.f), fmaxf(C2[mt][1][3], 0.f));
        float bb0 = sB3[bk], bb1 = sB3[bk + 1];
        C3[mt][0] = bb0; C3[mt][1] = bb1; C3[mt][2] = bb0; C3[mt][3] = bb1;
        mma16816(C3[mt], A3, B3h[0], B3h[1]);
        mma16816(C3[mt], A3, B3l[0], B3l[1]);
    }

    // ---- per-voxel weight (lane = voxel) ----
    float S = g_msum[v * (RESO * RESO) + j * RESO + k];
    float w = mask / (S + 1e-8f);
    s_w[v * 32 + lane] = w;

    // ---- scatter comp fragments to s_comp[ch][view][vox] ----
#pragma unroll
    for (int mt = 0; mt < 2; mt++) {
        int r0 = (lane >> 2) + mt * 16;
        s_comp[((bk    ) * NV + v) * 32 + r0    ] = C3[mt][0];
        s_comp[((bk + 1) * NV + v) * 32 + r0    ] = C3[mt][1];
        s_comp[((bk    ) * NV + v) * 32 + r0 + 8] = C3[mt][2];
        s_comp[((bk + 1) * NV + v) * 32 + r0 + 8] = C3[mt][3];
    }

    __syncthreads();

    // ---- Reduction across views: mean then variance ----
    int vox2 = tid & 31;
    int ch   = tid >> 5;  // 0..7
    float mean = 0.f;
#pragma unroll
    for (int v2 = 0; v2 < NV; v2++)
        mean += s_w[v2 * 32 + vox2] * s_comp[(ch * NV + v2) * 32 + vox2];
    float var = 0.f;
#pragma unroll
    for (int v2 = 0; v2 < NV; v2++) {
        float d = s_comp[(ch * NV + v2) * 32 + vox2] - mean;
        var += s_w[v2 * 32 + vox2] * d * d;
    }

    int i_out = blockIdx.x * 32 + vox2;
    out[(( ch      * RESO + k) * RESO + j) * RESO + i_out] = mean;
    out[(((ch + 8) * RESO + k) * RESO + j) * RESO + i_out] = var;
}

// ---------------------------------------------------------------------------
extern "C" void kernel_launch(void* const* d_in, const int* in_sizes, int n_in,
                              void* d_out, int out_size) {
    const float* feats = (const float*)d_in[0];
    const float* poses = (const float*)d_in[1];
    const float* Ks    = (const float*)d_in[2];
    const float* bbox  = (const float*)d_in[3];
    const int*   ph    = (const int*)d_in[4];
    const int*   pw    = (const int*)d_in[5];
    const float* W1 = (const float*)d_in[6];
    const float* b1 = (const float*)d_in[7];
    const float* W2 = (const float*)d_in[8];
    const float* b2 = (const float*)d_in[9];
    const float* W3 = (const float*)d_in[10];
    const float* b3 = (const float*)d_in[11];
    float* out = (float*)d_out;

    prep_kernel<<<GEMM_BLOCKS + (NV * RESO * RESO) / 256, 256>>>(
        feats, W1, b1, Ks, poses, bbox, ph, pw);

    dim3 mg(RESO / 32, RESO, RESO);
    fv_main<<<mg, 256>>>(Ks, poses, bbox, ph, pw, W2, b2, W3, b3, out);
}

// round 7
// speedup vs baseline: 4.1777x; 1.2413x over previous
#include <cuda_runtime.h>
#include <cuda_fp16.h>

#define NV   8
#define C_CH 32
#define H_F  128
#define W_F  128
#define HW_F (H_F * W_F)
#define RESO 64

#define VOXEL_F ((float)(0.3/64.0))
#define HALF_F  ((float)(0.3/128.0))

typedef unsigned long long u64;
typedef unsigned u32;

// ---- packed f32x2 helpers ----
__device__ __forceinline__ u64 pack2(float lo, float hi) {
    u64 r; asm("mov.b64 %0, {%1, %2};" : "=l"(r) : "f"(lo), "f"(hi)); return r;
}
__device__ __forceinline__ float2 unpack2(u64 p) {
    float2 r; asm("mov.b64 {%0, %1}, %2;" : "=f"(r.x), "=f"(r.y) : "l"(p)); return r;
}
__device__ __forceinline__ void ffma2(u64& d, u64 a, u64 b) {
    asm("fma.rn.f32x2 %0, %1, %2, %0;" : "+l"(d) : "l"(a), "l"(b));
}
__device__ __forceinline__ u32 pack_h2(float lo, float hi) {
    u32 r; asm("cvt.rn.f16x2.f32 %0, %1, %2;" : "=r"(r) : "f"(hi), "f"(lo)); return r;
}
__device__ __forceinline__ u32 f32x2_to_f16x2(u64 p) {
    float2 t = unpack2(p);
    return pack_h2(t.x, t.y);
}
__device__ __forceinline__ float rhalf(float x) {
    return __half2float(__float2half_rn(x));
}

// ---- tensor-core helpers ----
__device__ __forceinline__ void ldsm_x4(u32& r0, u32& r1, u32& r2, u32& r3, u32 addr) {
    asm volatile("ldmatrix.sync.aligned.m8n8.x4.shared.b16 {%0,%1,%2,%3}, [%4];"
                 : "=r"(r0), "=r"(r1), "=r"(r2), "=r"(r3) : "r"(addr));
}
__device__ __forceinline__ void mma16816(float* c, const u32* a, u32 b0, u32 b1) {
    asm volatile("mma.sync.aligned.m16n8k16.row.col.f32.f16.f16.f32 "
                 "{%0,%1,%2,%3}, {%4,%5,%6,%7}, {%8,%9}, {%0,%1,%2,%3};"
                 : "+f"(c[0]), "+f"(c[1]), "+f"(c[2]), "+f"(c[3])
                 : "r"(a[0]), "r"(a[1]), "r"(a[2]), "r"(a[3]), "r"(b0), "r"(b1));
}

// Scratch
__device__ __align__(16) u32 g_Gh[4 * NV * HW_F * 4];   // fp16 plane-split G
__device__ float g_msum[NV * RESO * RESO];
__device__ __align__(16) u32 g_frag[7 * 32 * 4];        // per-lane MMA weight/bias frags
__device__ float g_M[NV * 12];                          // per-view projection matrices

#define GEMM_BLOCKS 512
#define MSUM_BLOCKS 128

// ---------------------------------------------------------------------------
// Prep kernel: [0,512) per-pixel GEMM; [512,640) msum; block 640 = fragment +
// projection-matrix precompute.
// ---------------------------------------------------------------------------
__global__ __launch_bounds__(256)
void prep_kernel(const float* __restrict__ feats,
                 const float* __restrict__ W1,
                 const float* __restrict__ b1,
                 const float* __restrict__ Ks,
                 const float* __restrict__ poses,
                 const float* __restrict__ bbox,
                 const int* __restrict__ ph,
                 const int* __restrict__ pw,
                 const float* __restrict__ W2, const float* __restrict__ b2,
                 const float* __restrict__ W3, const float* __restrict__ b3) {
    int tid = threadIdx.x;
    if (blockIdx.x < GEMM_BLOCKS) {
        __shared__ __align__(16) float sW1[C_CH * C_CH];
        __shared__ __align__(16) float sB1[C_CH];
        for (int t = tid; t < 1024; t += 256) sW1[t] = W1[t];
        if (tid < 32) sB1[tid] = b1[tid];
        __syncthreads();

        int p  = blockIdx.x * 256 + tid;
        int v  = p >> 14;
        int pl = p & (HW_F - 1);
        const float* fp = feats + (size_t)v * C_CH * HW_F + pl;

        u64 acc[16];
        const u64* sB1p = (const u64*)sB1;
#pragma unroll
        for (int q = 0; q < 16; q++) acc[q] = sB1p[q];

#pragma unroll
        for (int c = 0; c < 32; c++) {
            float f = fp[c * HW_F];
            u64 f2 = pack2(f, f);
            const ulonglong2* wr = (const ulonglong2*)(sW1 + c * 32);
#pragma unroll
            for (int j4 = 0; j4 < 8; j4++) {
                ulonglong2 w = wr[j4];
                ffma2(acc[j4 * 2 + 0], f2, w.x);
                ffma2(acc[j4 * 2 + 1], f2, w.y);
            }
        }

        uint4* gbase = (uint4*)g_Gh;
#pragma unroll
        for (int pp = 0; pp < 4; pp++) {
            uint4 o;
            o.x = f32x2_to_f16x2(acc[pp * 4 + 0]);
            o.y = f32x2_to_f16x2(acc[pp * 4 + 1]);
            o.z = f32x2_to_f16x2(acc[pp * 4 + 2]);
            o.w = f32x2_to_f16x2(acc[pp * 4 + 3]);
            gbase[(size_t)pp * (NV * HW_F) + p] = o;
        }
    } else if (blockIdx.x < GEMM_BLOCKS + MSUM_BLOCKS) {
        int idx = (blockIdx.x - GEMM_BLOCKS) * 256 + tid;   // 0..32767
        int k = idx & 63, j = (idx >> 6) & 63, v = idx >> 12;

        const float* K = Ks + v * 9;
        const float* P = poses + v * 12;
        float M[12];
#pragma unroll
        for (int r = 0; r < 3; r++)
#pragma unroll
            for (int c = 0; c < 4; c++)
                M[r * 4 + c] = K[r * 3 + 0] * P[0 * 4 + c] +
                               K[r * 3 + 1] * P[1 * 4 + c] +
                               K[r * 3 + 2] * P[2 * 4 + c];

        float img_wf = (float)(*pw), img_hf = (float)(*ph);
        float y = (float)j * VOXEL_F + HALF_F + bbox[1];
        float z = (float)k * VOXEL_F + HALF_F + bbox[2];

        float s = 0.f;
        for (int i = 0; i < RESO; i++) {
            float x  = (float)i * VOXEL_F + HALF_F + bbox[0];
            float px = M[0] * x + M[1] * y + M[2]  * z + M[3];
            float py = M[4] * x + M[5] * y + M[6]  * z + M[7];
            float pz = M[8] * x + M[9] * y + M[10] * z + M[11];
            float u  = px / pz, vv = py / pz;
            float gx = u / img_wf - 1.f, gy = vv / img_hf - 1.f;
            float ix = (gx + 1.f) * 0.5f * (float)(W_F - 1);
            float iy = (gy + 1.f) * 0.5f * (float)(H_F - 1);
            float m = (ix >= 0.f && ix <= (float)(W_F - 1) &&
                       iy >= 0.f && iy <= (float)(H_F - 1) && pz > 0.f) ? 1.f : 0.f;
            s += m;
        }
        g_msum[idx] = s;
    } else {
        // fragment + M precompute
        if (tid < 32) {
            int lane = tid;
            int bn = lane >> 2;
            int bk = (lane & 3) * 2;
            u32 fr[28];
#pragma unroll
            for (int kt = 0; kt < 2; kt++)
#pragma unroll
                for (int nt = 0; nt < 2; nt++) {
                    int n = bn + nt * 8;
                    int k0 = bk + kt * 16;
                    float w0 = W2[(k0    ) * 16 + n];
                    float w1 = W2[(k0 + 1) * 16 + n];
                    float w8 = W2[(k0 + 8) * 16 + n];
                    float w9 = W2[(k0 + 9) * 16 + n];
                    fr[    kt * 4 + nt * 2 + 0] = pack_h2(w0, w1);
                    fr[    kt * 4 + nt * 2 + 1] = pack_h2(w8, w9);
                    fr[8 + kt * 4 + nt * 2 + 0] = pack_h2(w0 - rhalf(w0), w1 - rhalf(w1));
                    fr[8 + kt * 4 + nt * 2 + 1] = pack_h2(w8 - rhalf(w8), w9 - rhalf(w9));
                }
            {
                float w0 = W3[(bk    ) * 8 + bn];
                float w1 = W3[(bk + 1) * 8 + bn];
                float w8 = W3[(bk + 8) * 8 + bn];
                float w9 = W3[(bk + 9) * 8 + bn];
                fr[16] = pack_h2(w0, w1);
                fr[17] = pack_h2(w8, w9);
                fr[18] = pack_h2(w0 - rhalf(w0), w1 - rhalf(w1));
                fr[19] = pack_h2(w8 - rhalf(w8), w9 - rhalf(w9));
            }
            fr[20] = __float_as_uint(b2[bk]);
            fr[21] = __float_as_uint(b2[bk + 1]);
            fr[22] = __float_as_uint(b2[8 + bk]);
            fr[23] = __float_as_uint(b2[8 + bk + 1]);
            fr[24] = __float_as_uint(b3[bk]);
            fr[25] = __float_as_uint(b3[bk + 1]);
            fr[26] = 0; fr[27] = 0;
#pragma unroll
            for (int c4 = 0; c4 < 7; c4++)
#pragma unroll
                for (int r = 0; r < 4; r++)
                    g_frag[(c4 * 32 + lane) * 4 + r] = fr[c4 * 4 + r];
        } else if (tid < 128 + 32 && tid >= 32) {
            int e = tid - 32;
            if (e < 96) {
                int v = e / 12, q = e % 12, r = q >> 2, c = q & 3;
                const float* K = Ks + v * 9;
                const float* P = poses + v * 12;
                g_M[e] = K[r * 3 + 0] * P[0 + c] + K[r * 3 + 1] * P[4 + c] +
                         K[r * 3 + 2] * P[8 + c];
            }
        }
    }
}

// ---------------------------------------------------------------------------
// Main fused kernel.
// ---------------------------------------------------------------------------
#define ROWB 80          // staging row stride (bytes)
#define CSTR 260         // s_comp per-channel stride (floats): conflict-free

__global__ __launch_bounds__(256, 3)
void fv_main(const float* __restrict__ bbox,
             const int* __restrict__ ph,
             const int* __restrict__ pw,
             float* __restrict__ out) {
    __shared__ float sM[NV * 12];
    __shared__ float s_comp[8 * CSTR];
    __shared__ float s_w[NV * 32];
    __shared__ __align__(16) unsigned char sA[NV * 32 * ROWB];

    int tid = threadIdx.x;
    if (tid < 96) sM[tid] = g_M[tid];
    __syncthreads();

    int v    = tid >> 5;       // warp = view
    int lane = tid & 31;       // lane = voxel
    int i = blockIdx.x * 32 + lane;
    int j = blockIdx.y;
    int k = blockIdx.z;

    // ---- per-lane weight/bias fragments (coalesced, L1-resident) ----
    u32 fr[28];
    const uint4* gf = (const uint4*)g_frag;
#pragma unroll
    for (int c4 = 0; c4 < 7; c4++)
        *(uint4*)&fr[c4 * 4] = gf[c4 * 32 + lane];

    // ---- projection ----
    float x = (float)i * VOXEL_F + HALF_F + bbox[0];
    float y = (float)j * VOXEL_F + HALF_F + bbox[1];
    float z = (float)k * VOXEL_F + HALF_F + bbox[2];

    const float* M = sM + v * 12;
    float px = M[0] * x + M[1] * y + M[2]  * z + M[3];
    float py = M[4] * x + M[5] * y + M[6]  * z + M[7];
    float pz = M[8] * x + M[9] * y + M[10] * z + M[11];

    float img_wf = (float)(*pw), img_hf = (float)(*ph);
    float u  = px / pz, vv = py / pz;
    float gx = u / img_wf - 1.f, gy = vv / img_hf - 1.f;
    float ix = (gx + 1.f) * 0.5f * (float)(W_F - 1);
    float iy = (gy + 1.f) * 0.5f * (float)(H_F - 1);

    float ix0 = floorf(ix), iy0 = floorf(iy);
    float ax = ix - ix0, ay = iy - iy0;
    float wnw = (1.f - ax) * (1.f - ay);
    float wne = ax * (1.f - ay);
    float wsw = (1.f - ax) * ay;
    float wse = ax * ay;
    float mask = (ix >= 0.f && ix <= (float)(W_F - 1) &&
                  iy >= 0.f && iy <= (float)(H_F - 1) && pz > 0.f) ? 1.f : 0.f;

    int cx0 = (int)fminf(fmaxf(ix0,       0.f), (float)(W_F - 1));
    int cx1 = (int)fminf(fmaxf(ix0 + 1.f, 0.f), (float)(W_F - 1));
    int cy0 = (int)fminf(fmaxf(iy0,       0.f), (float)(H_F - 1));
    int cy1 = (int)fminf(fmaxf(iy0 + 1.f, 0.f), (float)(H_F - 1));

    int p00 = (v * H_F + cy0) * W_F + cx0;
    int p01 = (v * H_F + cy0) * W_F + cx1;
    int p10 = (v * H_F + cy1) * W_F + cx0;
    int p11 = (v * H_F + cy1) * W_F + cx1;

    __half2 wnwh = __float2half2_rn(wnw);
    __half2 wneh = __float2half2_rn(wne);
    __half2 wswh = __float2half2_rn(wsw);
    __half2 wseh = __float2half2_rn(wse);
    __half2 zeroh = __float2half2_rn(0.f);

    // ---- gather + interp + ReLU -> h1 staging ----
    unsigned char* myrow = sA + (v * 32 + lane) * ROWB;
    const uint4* gbase = (const uint4*)g_Gh;
#pragma unroll
    for (int pp = 0; pp < 4; pp++) {
        const uint4* plane = gbase + (size_t)pp * (NV * HW_F);
        uint4 a = plane[p00], b = plane[p01], c = plane[p10], d = plane[p11];
        const u32* au = &a.x; const u32* bu = &b.x;
        const u32* cu = &c.x; const u32* du = &d.x;
        u32 hq[4];
#pragma unroll
        for (int q = 0; q < 4; q++) {
            __half2 ha = *(const __half2*)&au[q];
            __half2 hb = *(const __half2*)&bu[q];
            __half2 hc = *(const __half2*)&cu[q];
            __half2 hd = *(const __half2*)&du[q];
            __half2 r = __hmul2(wnwh, ha);
            r = __hfma2(wneh, hb, r);
            r = __hfma2(wswh, hc, r);
            r = __hfma2(wseh, hd, r);
            r = __hmax2(r, zeroh);
            hq[q] = *(const u32*)&r;
        }
        ((uint4*)myrow)[pp] = make_uint4(hq[0], hq[1], hq[2], hq[3]);
    }

    int bn = lane >> 2;
    int bk = (lane & 3) * 2;

    __syncwarp();

    // ---- A fragments ----
    u32 abase = (u32)__cvta_generic_to_shared(sA + v * 32 * ROWB);
    u32 laddr = abase + (lane & 15) * ROWB + ((lane >> 4) << 4);
    u32 A[2][2][4];
#pragma unroll
    for (int mt = 0; mt < 2; mt++)
#pragma unroll
        for (int kt = 0; kt < 2; kt++)
            ldsm_x4(A[mt][kt][0], A[mt][kt][1], A[mt][kt][2], A[mt][kt][3],
                    laddr + mt * 16 * ROWB + kt * 32);

    // ---- layer 2 (16 HMMA, hi+lo weight split) ----
    float C2[2][2][4];
#pragma unroll
    for (int mt = 0; mt < 2; mt++)
#pragma unroll
        for (int nt = 0; nt < 2; nt++) {
            float bb0 = __uint_as_float(fr[20 + nt * 2]);
            float bb1 = __uint_as_float(fr[20 + nt * 2 + 1]);
            C2[mt][nt][0] = bb0; C2[mt][nt][1] = bb1;
            C2[mt][nt][2] = bb0; C2[mt][nt][3] = bb1;
        }
#pragma unroll
    for (int mt = 0; mt < 2; mt++)
#pragma unroll
        for (int nt = 0; nt < 2; nt++)
#pragma unroll
            for (int kt = 0; kt < 2; kt++) {
                mma16816(C2[mt][nt], A[mt][kt], fr[    kt * 4 + nt * 2], fr[    kt * 4 + nt * 2 + 1]);
                mma16816(C2[mt][nt], A[mt][kt], fr[8 + kt * 4 + nt * 2], fr[8 + kt * 4 + nt * 2 + 1]);
            }

    // ---- layer 3 (4 HMMA, fragment chaining) ----
    float C3[2][4];
#pragma unroll
    for (int mt = 0; mt < 2; mt++) {
        u32 A3[4];
        A3[0] = pack_h2(fmaxf(C2[mt][0][0], 0.f), fmaxf(C2[mt][0][1], 0.f));
        A3[1] = pack_h2(fmaxf(C2[mt][0][2], 0.f), fmaxf(C2[mt][0][3], 0.f));
        A3[2] = pack_h2(fmaxf(C2[mt][1][0], 0.f), fmaxf(C2[mt][1][1], 0.f));
        A3[3] = pack_h2(fmaxf(C2[mt][1][2], 0.f), fmaxf(C2[mt][1][3], 0.f));
        float bb0 = __uint_as_float(fr[24]);
        float bb1 = __uint_as_float(fr[25]);
        C3[mt][0] = bb0; C3[mt][1] = bb1; C3[mt][2] = bb0; C3[mt][3] = bb1;
        mma16816(C3[mt], A3, fr[16], fr[17]);
        mma16816(C3[mt], A3, fr[18], fr[19]);
    }

    // ---- weight ----
    float S = g_msum[v * (RESO * RESO) + j * RESO + k];
    float w = mask / (S + 1e-8f);
    s_w[v * 32 + lane] = w;

    // ---- scatter comp to s_comp (padded stride -> conflict-free) ----
#pragma unroll
    for (int mt = 0; mt < 2; mt++) {
        int r0 = (lane >> 2) + mt * 16;
        s_comp[(bk    ) * CSTR + v * 32 + r0    ] = C3[mt][0];
        s_comp[(bk + 1) * CSTR + v * 32 + r0    ] = C3[mt][1];
        s_comp[(bk    ) * CSTR + v * 32 + r0 + 8] = C3[mt][2];
        s_comp[(bk + 1) * CSTR + v * 32 + r0 + 8] = C3[mt][3];
    }

    __syncthreads();

    // ---- cross-view reduction ----
    int vox2 = tid & 31;
    int ch   = tid >> 5;
    float mean = 0.f;
#pragma unroll
    for (int v2 = 0; v2 < NV; v2++)
        mean += s_w[v2 * 32 + vox2] * s_comp[ch * CSTR + v2 * 32 + vox2];
    float var = 0.f;
#pragma unroll
    for (int v2 = 0; v2 < NV; v2++) {
        float d = s_comp[ch * CSTR + v2 * 32 + vox2] - mean;
        var += s_w[v2 * 32 + vox2] * d * d;
    }

    int i_out = blockIdx.x * 32 + vox2;
    out[(( ch      * RESO + k) * RESO + j) * RESO + i_out] = mean;
    out[(((ch + 8) * RESO + k) * RESO + j) * RESO + i_out] = var;
}

// ---------------------------------------------------------------------------
extern "C" void kernel_launch(void* const* d_in, const int* in_sizes, int n_in,
                              void* d_out, int out_size) {
    const float* feats = (const float*)d_in[0];
    const float* poses = (const float*)d_in[1];
    const float* Ks    = (const float*)d_in[2];
    const float* bbox  = (const float*)d_in[3];
    const int*   ph    = (const int*)d_in[4];
    const int*   pw    = (const int*)d_in[5];
    const float* W1 = (const float*)d_in[6];
    const float* b1 = (const float*)d_in[7];
    const float* W2 = (const float*)d_in[8];
    const float* b2 = (const float*)d_in[9];
    const float* W3 = (const float*)d_in[10];
    const float* b3 = (const float*)d_in[11];
    float* out = (float*)d_out;

    prep_kernel<<<GEMM_BLOCKS + MSUM_BLOCKS + 1, 256>>>(
        feats, W1, b1, Ks, poses, bbox, ph, pw, W2, b2, W3, b3);

    dim3 mg(RESO / 32, RESO, RESO);
    fv_main<<<mg, 256>>>(bbox, ph, pw, out);
}

// round 8
// speedup vs baseline: 4.5570x; 1.0908x over previous
#include <cuda_runtime.h>
#include <cuda_fp16.h>

#define NV   8
#define C_CH 32
#define H_F  128
#define W_F  128
#define HW_F (H_F * W_F)
#define RESO 64

#define VOXEL_F ((float)(0.3/64.0))
#define HALF_F  ((float)(0.3/128.0))

typedef unsigned long long u64;
typedef unsigned u32;

// ---- packed f32x2 helpers ----
__device__ __forceinline__ u64 pack2(float lo, float hi) {
    u64 r; asm("mov.b64 %0, {%1, %2};" : "=l"(r) : "f"(lo), "f"(hi)); return r;
}
__device__ __forceinline__ float2 unpack2(u64 p) {
    float2 r; asm("mov.b64 {%0, %1}, %2;" : "=f"(r.x), "=f"(r.y) : "l"(p)); return r;
}
__device__ __forceinline__ void ffma2(u64& d, u64 a, u64 b) {
    asm("fma.rn.f32x2 %0, %1, %2, %0;" : "+l"(d) : "l"(a), "l"(b));
}
__device__ __forceinline__ u32 pack_h2(float lo, float hi) {
    u32 r; asm("cvt.rn.f16x2.f32 %0, %1, %2;" : "=r"(r) : "f"(hi), "f"(lo)); return r;
}
__device__ __forceinline__ u32 f32x2_to_f16x2(u64 p) {
    float2 t = unpack2(p);
    return pack_h2(t.x, t.y);
}
__device__ __forceinline__ float rhalf(float x) {
    return __half2float(__float2half_rn(x));
}

// ---- tensor-core helpers ----
__device__ __forceinline__ void ldsm_x4(u32& r0, u32& r1, u32& r2, u32& r3, u32 addr) {
    asm volatile("ldmatrix.sync.aligned.m8n8.x4.shared.b16 {%0,%1,%2,%3}, [%4];"
                 : "=r"(r0), "=r"(r1), "=r"(r2), "=r"(r3) : "r"(addr));
}
__device__ __forceinline__ void mma16816(float* c, const u32* a, u32 b0, u32 b1) {
    asm volatile("mma.sync.aligned.m16n8k16.row.col.f32.f16.f16.f32 "
                 "{%0,%1,%2,%3}, {%4,%5,%6,%7}, {%8,%9}, {%0,%1,%2,%3};"
                 : "+f"(c[0]), "+f"(c[1]), "+f"(c[2]), "+f"(c[3])
                 : "r"(a[0]), "r"(a[1]), "r"(a[2]), "r"(a[3]), "r"(b0), "r"(b1));
}

// Scratch
__device__ __align__(16) u32 g_Gh[4 * NV * HW_F * 4];   // fp16 plane-split G
__device__ float g_msum[NV * RESO * RESO];
__device__ __align__(16) u32 g_frag[7 * 32 * 4];        // per-lane MMA weight/bias frags
__device__ float g_M[NV * 12];                          // per-view projection matrices

#define GEMM_BLOCKS 512
#define MSUM_BLOCKS 128

// ---------------------------------------------------------------------------
// Prep kernel: [0,512) per-pixel GEMM; [512,640) msum; block 640 = fragment +
// projection-matrix precompute.
// ---------------------------------------------------------------------------
__global__ __launch_bounds__(256)
void prep_kernel(const float* __restrict__ feats,
                 const float* __restrict__ W1,
                 const float* __restrict__ b1,
                 const float* __restrict__ Ks,
                 const float* __restrict__ poses,
                 const float* __restrict__ bbox,
                 const int* __restrict__ ph,
                 const int* __restrict__ pw,
                 const float* __restrict__ W2, const float* __restrict__ b2,
                 const float* __restrict__ W3, const float* __restrict__ b3) {
    int tid = threadIdx.x;
    if (blockIdx.x < GEMM_BLOCKS) {
        __shared__ __align__(16) float sW1[C_CH * C_CH];
        __shared__ __align__(16) float sB1[C_CH];
        for (int t = tid; t < 1024; t += 256) sW1[t] = W1[t];
        if (tid < 32) sB1[tid] = b1[tid];
        __syncthreads();

        int p  = blockIdx.x * 256 + tid;
        int v  = p >> 14;
        int pl = p & (HW_F - 1);
        const float* fp = feats + (size_t)v * C_CH * HW_F + pl;

        u64 acc[16];
        const u64* sB1p = (const u64*)sB1;
#pragma unroll
        for (int q = 0; q < 16; q++) acc[q] = sB1p[q];

#pragma unroll
        for (int c = 0; c < 32; c++) {
            float f = fp[c * HW_F];
            u64 f2 = pack2(f, f);
            const ulonglong2* wr = (const ulonglong2*)(sW1 + c * 32);
#pragma unroll
            for (int j4 = 0; j4 < 8; j4++) {
                ulonglong2 w = wr[j4];
                ffma2(acc[j4 * 2 + 0], f2, w.x);
                ffma2(acc[j4 * 2 + 1], f2, w.y);
            }
        }

        uint4* gbase = (uint4*)g_Gh;
#pragma unroll
        for (int pp = 0; pp < 4; pp++) {
            uint4 o;
            o.x = f32x2_to_f16x2(acc[pp * 4 + 0]);
            o.y = f32x2_to_f16x2(acc[pp * 4 + 1]);
            o.z = f32x2_to_f16x2(acc[pp * 4 + 2]);
            o.w = f32x2_to_f16x2(acc[pp * 4 + 3]);
            gbase[(size_t)pp * (NV * HW_F) + p] = o;
        }
    } else if (blockIdx.x < GEMM_BLOCKS + MSUM_BLOCKS) {
        int idx = (blockIdx.x - GEMM_BLOCKS) * 256 + tid;   // 0..32767
        int k = idx & 63, j = (idx >> 6) & 63, v = idx >> 12;

        const float* K = Ks + v * 9;
        const float* P = poses + v * 12;
        float M[12];
#pragma unroll
        for (int r = 0; r < 3; r++)
#pragma unroll
            for (int c = 0; c < 4; c++)
                M[r * 4 + c] = K[r * 3 + 0] * P[0 * 4 + c] +
                               K[r * 3 + 1] * P[1 * 4 + c] +
                               K[r * 3 + 2] * P[2 * 4 + c];

        float img_wf = (float)(*pw), img_hf = (float)(*ph);
        float y = (float)j * VOXEL_F + HALF_F + bbox[1];
        float z = (float)k * VOXEL_F + HALF_F + bbox[2];

        float s = 0.f;
        for (int i = 0; i < RESO; i++) {
            float x  = (float)i * VOXEL_F + HALF_F + bbox[0];
            float px = M[0] * x + M[1] * y + M[2]  * z + M[3];
            float py = M[4] * x + M[5] * y + M[6]  * z + M[7];
            float pz = M[8] * x + M[9] * y + M[10] * z + M[11];
            float u  = px / pz, vv = py / pz;
            float gx = u / img_wf - 1.f, gy = vv / img_hf - 1.f;
            float ix = (gx + 1.f) * 0.5f * (float)(W_F - 1);
            float iy = (gy + 1.f) * 0.5f * (float)(H_F - 1);
            float m = (ix >= 0.f && ix <= (float)(W_F - 1) &&
                       iy >= 0.f && iy <= (float)(H_F - 1) && pz > 0.f) ? 1.f : 0.f;
            s += m;
        }
        g_msum[idx] = s;
    } else {
        // fragment + M precompute
        if (tid < 32) {
            int lane = tid;
            int bn = lane >> 2;
            int bk = (lane & 3) * 2;
            u32 fr[28];
#pragma unroll
            for (int kt = 0; kt < 2; kt++)
#pragma unroll
                for (int nt = 0; nt < 2; nt++) {
                    int n = bn + nt * 8;
                    int k0 = bk + kt * 16;
                    float w0 = W2[(k0    ) * 16 + n];
                    float w1 = W2[(k0 + 1) * 16 + n];
                    float w8 = W2[(k0 + 8) * 16 + n];
                    float w9 = W2[(k0 + 9) * 16 + n];
                    fr[    kt * 4 + nt * 2 + 0] = pack_h2(w0, w1);
                    fr[    kt * 4 + nt * 2 + 1] = pack_h2(w8, w9);
                    fr[8 + kt * 4 + nt * 2 + 0] = pack_h2(w0 - rhalf(w0), w1 - rhalf(w1));
                    fr[8 + kt * 4 + nt * 2 + 1] = pack_h2(w8 - rhalf(w8), w9 - rhalf(w9));
                }
            {
                float w0 = W3[(bk    ) * 8 + bn];
                float w1 = W3[(bk + 1) * 8 + bn];
                float w8 = W3[(bk + 8) * 8 + bn];
                float w9 = W3[(bk + 9) * 8 + bn];
                fr[16] = pack_h2(w0, w1);
                fr[17] = pack_h2(w8, w9);
                fr[18] = pack_h2(w0 - rhalf(w0), w1 - rhalf(w1));
                fr[19] = pack_h2(w8 - rhalf(w8), w9 - rhalf(w9));
            }
            fr[20] = __float_as_uint(b2[bk]);
            fr[21] = __float_as_uint(b2[bk + 1]);
            fr[22] = __float_as_uint(b2[8 + bk]);
            fr[23] = __float_as_uint(b2[8 + bk + 1]);
            fr[24] = __float_as_uint(b3[bk]);
            fr[25] = __float_as_uint(b3[bk + 1]);
            fr[26] = 0; fr[27] = 0;
#pragma unroll
            for (int c4 = 0; c4 < 7; c4++)
#pragma unroll
                for (int r = 0; r < 4; r++)
                    g_frag[(c4 * 32 + lane) * 4 + r] = fr[c4 * 4 + r];
        } else if (tid < 128 + 32 && tid >= 32) {
            int e = tid - 32;
            if (e < 96) {
                int v = e / 12, q = e % 12, r = q >> 2, c = q & 3;
                const float* K = Ks + v * 9;
                const float* P = poses + v * 12;
                g_M[e] = K[r * 3 + 0] * P[0 + c] + K[r * 3 + 1] * P[4 + c] +
                         K[r * 3 + 2] * P[8 + c];
            }
        }
    }
}

// ---------------------------------------------------------------------------
// Main fused kernel.
// ---------------------------------------------------------------------------
#define ROWB 80          // staging row stride (bytes)
#define CSTR 260         // s_comp per-channel stride (floats): conflict-free

__global__ __launch_bounds__(256, 4)
void fv_main(const float* __restrict__ bbox,
             const int* __restrict__ ph,
             const int* __restrict__ pw,
             float* __restrict__ out) {
    __shared__ float sM[NV * 12];
    __shared__ float s_comp[8 * CSTR];
    __shared__ float s_w[NV * 32];
    __shared__ __align__(16) unsigned char sA[NV * 32 * ROWB];

    int tid = threadIdx.x;
    if (tid < 96) sM[tid] = g_M[tid];
    __syncthreads();

    int v    = tid >> 5;       // warp = view
    int lane = tid & 31;       // lane = voxel
    int i = blockIdx.x * 32 + lane;
    int j = blockIdx.y;
    int k = blockIdx.z;

    // ---- projection ----
    float x = (float)i * VOXEL_F + HALF_F + bbox[0];
    float y = (float)j * VOXEL_F + HALF_F + bbox[1];
    float z = (float)k * VOXEL_F + HALF_F + bbox[2];

    const float* M = sM + v * 12;
    float px = M[0] * x + M[1] * y + M[2]  * z + M[3];
    float py = M[4] * x + M[5] * y + M[6]  * z + M[7];
    float pz = M[8] * x + M[9] * y + M[10] * z + M[11];

    float img_wf = (float)(*pw), img_hf = (float)(*ph);
    float u  = px / pz, vv = py / pz;
    float gx = u / img_wf - 1.f, gy = vv / img_hf - 1.f;
    float ix = (gx + 1.f) * 0.5f * (float)(W_F - 1);
    float iy = (gy + 1.f) * 0.5f * (float)(H_F - 1);

    float ix0 = floorf(ix), iy0 = floorf(iy);
    float ax = ix - ix0, ay = iy - iy0;
    float wnw = (1.f - ax) * (1.f - ay);
    float wne = ax * (1.f - ay);
    float wsw = (1.f - ax) * ay;
    float wse = ax * ay;
    float mask = (ix >= 0.f && ix <= (float)(W_F - 1) &&
                  iy >= 0.f && iy <= (float)(H_F - 1) && pz > 0.f) ? 1.f : 0.f;

    int cx0 = (int)fminf(fmaxf(ix0,       0.f), (float)(W_F - 1));
    int cx1 = (int)fminf(fmaxf(ix0 + 1.f, 0.f), (float)(W_F - 1));
    int cy0 = (int)fminf(fmaxf(iy0,       0.f), (float)(H_F - 1));
    int cy1 = (int)fminf(fmaxf(iy0 + 1.f, 0.f), (float)(H_F - 1));

    int p00 = (v * H_F + cy0) * W_F + cx0;
    int p01 = (v * H_F + cy0) * W_F + cx1;
    int p10 = (v * H_F + cy1) * W_F + cx0;
    int p11 = (v * H_F + cy1) * W_F + cx1;

    __half2 wnwh = __float2half2_rn(wnw);
    __half2 wneh = __float2half2_rn(wne);
    __half2 wswh = __float2half2_rn(wsw);
    __half2 wseh = __float2half2_rn(wse);
    __half2 zeroh = __float2half2_rn(0.f);

    // ---- gather + interp + ReLU -> h1 staging ----
    unsigned char* myrow = sA + (v * 32 + lane) * ROWB;
    const uint4* gbase = (const uint4*)g_Gh;
#pragma unroll
    for (int pp = 0; pp < 4; pp++) {
        const uint4* plane = gbase + (size_t)pp * (NV * HW_F);
        uint4 a = plane[p00], b = plane[p01], c = plane[p10], d = plane[p11];
        const u32* au = &a.x; const u32* bu = &b.x;
        const u32* cu = &c.x; const u32* du = &d.x;
        u32 hq[4];
#pragma unroll
        for (int q = 0; q < 4; q++) {
            __half2 ha = *(const __half2*)&au[q];
            __half2 hb = *(const __half2*)&bu[q];
            __half2 hc = *(const __half2*)&cu[q];
            __half2 hd = *(const __half2*)&du[q];
            __half2 r = __hmul2(wnwh, ha);
            r = __hfma2(wneh, hb, r);
            r = __hfma2(wswh, hc, r);
            r = __hfma2(wseh, hd, r);
            r = __hmax2(r, zeroh);
            hq[q] = *(const u32*)&r;
        }
        ((uint4*)myrow)[pp] = make_uint4(hq[0], hq[1], hq[2], hq[3]);
    }

    int bn = lane >> 2;
    int bk = (lane & 3) * 2;

    __syncwarp();

    // ---- A fragments ----
    u32 abase = (u32)__cvta_generic_to_shared(sA + v * 32 * ROWB);
    u32 laddr = abase + (lane & 15) * ROWB + ((lane >> 4) << 4);
    u32 A[2][2][4];
#pragma unroll
    for (int mt = 0; mt < 2; mt++)
#pragma unroll
        for (int kt = 0; kt < 2; kt++)
            ldsm_x4(A[mt][kt][0], A[mt][kt][1], A[mt][kt][2], A[mt][kt][3],
                    laddr + mt * 16 * ROWB + kt * 32);

    // ---- layer 2 (16 HMMA, hi+lo weight split); fragments loaded at use
    //      from g_frag (L1-resident) to keep register pressure low ----
    const uint4* gf = (const uint4*)g_frag;
    float C2[2][2][4];
    {
        uint4 fb2 = gf[5 * 32 + lane];          // b2 biases
#pragma unroll
        for (int mt = 0; mt < 2; mt++) {
            C2[mt][0][0] = __uint_as_float(fb2.x); C2[mt][0][1] = __uint_as_float(fb2.y);
            C2[mt][0][2] = __uint_as_float(fb2.x); C2[mt][0][3] = __uint_as_float(fb2.y);
            C2[mt][1][0] = __uint_as_float(fb2.z); C2[mt][1][1] = __uint_as_float(fb2.w);
            C2[mt][1][2] = __uint_as_float(fb2.z); C2[mt][1][3] = __uint_as_float(fb2.w);
        }
    }
#pragma unroll
    for (int hl = 0; hl < 2; hl++) {            // hi then lo weights
#pragma unroll
        for (int kt = 0; kt < 2; kt++) {
            uint4 fw = gf[(hl * 2 + kt) * 32 + lane];   // [b0n0,b1n0,b0n1,b1n1]
#pragma unroll
            for (int mt = 0; mt < 2; mt++) {
                mma16816(C2[mt][0], A[mt][kt], fw.x, fw.y);
                mma16816(C2[mt][1], A[mt][kt], fw.z, fw.w);
            }
        }
    }

    // ---- layer 3 (4 HMMA, fragment chaining) ----
    float C3[2][4];
    {
        uint4 f3 = gf[4 * 32 + lane];           // B3 hi (x,y) + lo (z,w)
        uint4 f6 = gf[6 * 32 + lane];           // b3 biases in x,y
        float bb0 = __uint_as_float(f6.x);
        float bb1 = __uint_as_float(f6.y);
#pragma unroll
        for (int mt = 0; mt < 2; mt++) {
            u32 A3[4];
            A3[0] = pack_h2(fmaxf(C2[mt][0][0], 0.f), fmaxf(C2[mt][0][1], 0.f));
            A3[1] = pack_h2(fmaxf(C2[mt][0][2], 0.f), fmaxf(C2[mt][0][3], 0.f));
            A3[2] = pack_h2(fmaxf(C2[mt][1][0], 0.f), fmaxf(C2[mt][1][1], 0.f));
            A3[3] = pack_h2(fmaxf(C2[mt][1][2], 0.f), fmaxf(C2[mt][1][3], 0.f));
            C3[mt][0] = bb0; C3[mt][1] = bb1; C3[mt][2] = bb0; C3[mt][3] = bb1;
            mma16816(C3[mt], A3, f3.x, f3.y);
            mma16816(C3[mt], A3, f3.z, f3.w);
        }
    }

    // ---- weight ----
    float S = g_msum[v * (RESO * RESO) + j * RESO + k];
    float w = mask / (S + 1e-8f);
    s_w[v * 32 + lane] = w;

    // ---- scatter comp to s_comp (padded stride -> conflict-free) ----
#pragma unroll
    for (int mt = 0; mt < 2; mt++) {
        int r0 = (lane >> 2) + mt * 16;
        s_comp[(bk    ) * CSTR + v * 32 + r0    ] = C3[mt][0];
        s_comp[(bk + 1) * CSTR + v * 32 + r0    ] = C3[mt][1];
        s_comp[(bk    ) * CSTR + v * 32 + r0 + 8] = C3[mt][2];
        s_comp[(bk + 1) * CSTR + v * 32 + r0 + 8] = C3[mt][3];
    }

    __syncthreads();

    // ---- cross-view reduction ----
    int vox2 = tid & 31;
    int ch   = tid >> 5;
    float mean = 0.f;
#pragma unroll
    for (int v2 = 0; v2 < NV; v2++)
        mean += s_w[v2 * 32 + vox2] * s_comp[ch * CSTR + v2 * 32 + vox2];
    float var = 0.f;
#pragma unroll
    for (int v2 = 0; v2 < NV; v2++) {
        float d = s_comp[ch * CSTR + v2 * 32 + vox2] - mean;
        var += s_w[v2 * 32 + vox2] * d * d;
    }

    int i_out = blockIdx.x * 32 + vox2;
    out[(( ch      * RESO + k) * RESO + j) * RESO + i_out] = mean;
    out[(((ch + 8) * RESO + k) * RESO + j) * RESO + i_out] = var;
}

// ---------------------------------------------------------------------------
extern "C" void kernel_launch(void* const* d_in, const int* in_sizes, int n_in,
                              void* d_out, int out_size) {
    const float* feats = (const float*)d_in[0];
    const float* poses = (const float*)d_in[1];
    const float* Ks    = (const float*)d_in[2];
    const float* bbox  = (const float*)d_in[3];
    const int*   ph    = (const int*)d_in[4];
    const int*   pw    = (const int*)d_in[5];
    const float* W1 = (const float*)d_in[6];
    const float* b1 = (const float*)d_in[7];
    const float* W2 = (const float*)d_in[8];
    const float* b2 = (const float*)d_in[9];
    const float* W3 = (const float*)d_in[10];
    const float* b3 = (const float*)d_in[11];
    float* out = (float*)d_out;

    prep_kernel<<<GEMM_BLOCKS + MSUM_BLOCKS + 1, 256>>>(
        feats, W1, b1, Ks, poses, bbox, ph, pw, W2, b2, W3, b3);

    dim3 mg(RESO / 32, RESO, RESO);
    fv_main<<<mg, 256>>>(bbox, ph, pw, out);
}